// round 1
// baseline (speedup 1.0000x reference)
#include <cuda_runtime.h>
#include <math.h>

#define B_   4
#define L_   2048
#define D_   1024
#define H_   16
#define DK_  64
#define DFF_ 4096
#define M_   (B_*L_)    // 8192 rows
#define BH_  (B_*H_)    // 64

// ---------------- scratch (static device globals; no allocation) ----------------
__device__ float g_x[M_*D_];        // LN1 output
__device__ float g_q[BH_*L_*DK_];
__device__ float g_k[BH_*L_*DK_];
__device__ float g_v[BH_*L_*DK_];
__device__ float g_o[M_*D_];        // attention output (b,l,h*dv)
__device__ float g_y[M_*D_];        // after fc residual
__device__ float g_z[M_*D_];        // LN2 output
__device__ float g_h[M_*DFF_];      // FFN hidden
__device__ float g_rowsum[BH_*L_];  // softmax denominators

// ---------------- LayerNorm: one block per row of 1024 ----------------
__global__ __launch_bounds__(256) void ln_kernel(const float* __restrict__ in,
                                                 const float* __restrict__ g,
                                                 const float* __restrict__ b,
                                                 float* __restrict__ out) {
    int row = blockIdx.x;
    const float4* inr = (const float4*)(in + (size_t)row * D_);
    float4 v = inr[threadIdx.x];
    float s  = v.x + v.y + v.z + v.w;
    float ss = v.x*v.x + v.y*v.y + v.z*v.z + v.w*v.w;
    #pragma unroll
    for (int o = 16; o > 0; o >>= 1) {
        s  += __shfl_xor_sync(0xffffffffu, s,  o);
        ss += __shfl_xor_sync(0xffffffffu, ss, o);
    }
    __shared__ float red[16];
    __shared__ float mv[2];
    int w = threadIdx.x >> 5, ln = threadIdx.x & 31;
    if (ln == 0) { red[w] = s; red[w + 8] = ss; }
    __syncthreads();
    if (threadIdx.x == 0) {
        float a = 0.f, q = 0.f;
        #pragma unroll
        for (int i = 0; i < 8; i++) { a += red[i]; q += red[i + 8]; }
        float mu = a * (1.0f / D_);
        mv[0] = mu;
        mv[1] = rsqrtf(q * (1.0f / D_) - mu * mu + 1e-6f);
    }
    __syncthreads();
    float mu = mv[0], rs = mv[1];
    float4 gg = ((const float4*)g)[threadIdx.x];
    float4 bb = ((const float4*)b)[threadIdx.x];
    float4 o4;
    o4.x = (v.x - mu) * rs * gg.x + bb.x;
    o4.y = (v.y - mu) * rs * gg.y + bb.y;
    o4.z = (v.z - mu) * rs * gg.z + bb.z;
    o4.w = (v.w - mu) * rs * gg.w + bb.w;
    ((float4*)(out + (size_t)row * D_))[threadIdx.x] = o4;
}

// ---------------- Tiled fp32 NT GEMM: C[m,n] = sum_k A[m,k]*B[n,k] + epilogue ----------------
// 128x128 block tile, BK=16, 256 threads, 8x8 per thread.
enum { EPI_QKV = 0, EPI_RES = 1, EPI_BIAS_RELU = 2, EPI_BIAS_RES = 3 };

template <int EPI>
__global__ __launch_bounds__(256) void gemm_nt(const float* __restrict__ A,
                                               const float* __restrict__ Bw,
                                               float* __restrict__ C,
                                               const float* __restrict__ bias,
                                               const float* __restrict__ res,
                                               int M, int N, int K) {
    __shared__ float As[16][128];
    __shared__ float Bs[16][128];
    const int bm = blockIdx.y * 128, bn = blockIdx.x * 128;
    const int tid = threadIdx.x;
    const int tx = tid & 15, ty = tid >> 4;
    const int lr = tid >> 2;          // 0..63
    const int lc = (tid & 3) * 4;     // 0,4,8,12

    float acc[8][8];
    #pragma unroll
    for (int i = 0; i < 8; i++)
        #pragma unroll
        for (int j = 0; j < 8; j++) acc[i][j] = 0.f;

    const float* Ap  = A  + (size_t)(bm + lr) * K + lc;
    const float* Ap2 = Ap + (size_t)64 * K;
    const float* Bp  = Bw + (size_t)(bn + lr) * K + lc;
    const float* Bp2 = Bp + (size_t)64 * K;

    for (int k0 = 0; k0 < K; k0 += 16) {
        float4 a0 = *(const float4*)(Ap  + k0);
        float4 a1 = *(const float4*)(Ap2 + k0);
        float4 b0 = *(const float4*)(Bp  + k0);
        float4 b1 = *(const float4*)(Bp2 + k0);
        __syncthreads();
        As[lc + 0][lr] = a0.x; As[lc + 1][lr] = a0.y; As[lc + 2][lr] = a0.z; As[lc + 3][lr] = a0.w;
        As[lc + 0][lr + 64] = a1.x; As[lc + 1][lr + 64] = a1.y; As[lc + 2][lr + 64] = a1.z; As[lc + 3][lr + 64] = a1.w;
        Bs[lc + 0][lr] = b0.x; Bs[lc + 1][lr] = b0.y; Bs[lc + 2][lr] = b0.z; Bs[lc + 3][lr] = b0.w;
        Bs[lc + 0][lr + 64] = b1.x; Bs[lc + 1][lr + 64] = b1.y; Bs[lc + 2][lr + 64] = b1.z; Bs[lc + 3][lr + 64] = b1.w;
        __syncthreads();
        #pragma unroll
        for (int kk = 0; kk < 16; kk++) {
            float av[8], bv[8];
            *(float4*)&av[0] = *(const float4*)&As[kk][ty * 8];
            *(float4*)&av[4] = *(const float4*)&As[kk][ty * 8 + 4];
            *(float4*)&bv[0] = *(const float4*)&Bs[kk][tx * 8];
            *(float4*)&bv[4] = *(const float4*)&Bs[kk][tx * 8 + 4];
            #pragma unroll
            for (int i = 0; i < 8; i++)
                #pragma unroll
                for (int j = 0; j < 8; j++)
                    acc[i][j] = fmaf(av[i], bv[j], acc[i][j]);
        }
    }

    #pragma unroll
    for (int i = 0; i < 8; i++) {
        int m = bm + ty * 8 + i;
        #pragma unroll
        for (int jj = 0; jj < 2; jj++) {
            int n = bn + tx * 8 + jj * 4;
            float4 r = make_float4(acc[i][jj*4], acc[i][jj*4+1], acc[i][jj*4+2], acc[i][jj*4+3]);
            if (EPI == EPI_QKV) {
                // remap [m,n] -> [b,h,l,d]
                int bb = m >> 11, l = m & 2047, hh = n >> 6, d = n & 63;
                *(float4*)(C + (((size_t)(bb * H_ + hh) * L_ + l) * DK_ + d)) = r;
            } else {
                size_t off = (size_t)m * N + n;
                if (EPI == EPI_RES) {
                    float4 rr = *(const float4*)(res + off);
                    r.x += rr.x; r.y += rr.y; r.z += rr.z; r.w += rr.w;
                }
                if (EPI == EPI_BIAS_RELU) {
                    float4 bbv = *(const float4*)(bias + n);
                    r.x = fmaxf(r.x + bbv.x, 0.f); r.y = fmaxf(r.y + bbv.y, 0.f);
                    r.z = fmaxf(r.z + bbv.z, 0.f); r.w = fmaxf(r.w + bbv.w, 0.f);
                }
                if (EPI == EPI_BIAS_RES) {
                    float4 bbv = *(const float4*)(bias + n);
                    float4 rr  = *(const float4*)(res + off);
                    r.x += bbv.x + rr.x; r.y += bbv.y + rr.y;
                    r.z += bbv.z + rr.z; r.w += bbv.w + rr.w;
                }
                *(float4*)(C + off) = r;
            }
        }
    }
}

// ---------------- Fused attention: per (b,h,64-query tile) ----------------
// S = (Q.K^T/8)*prior, mask, exp (no max-sub: logits are O(1)); writes
// unnormalized attn + rowsums, accumulates O = e @ V, normalizes O.
__global__ __launch_bounds__(256) void attn_kernel(const float* __restrict__ Q,
                                                   const float* __restrict__ K,
                                                   const float* __restrict__ V,
                                                   const float* __restrict__ prior,
                                                   const int* __restrict__ mask,
                                                   float* __restrict__ attn,
                                                   float* __restrict__ O,
                                                   float* __restrict__ rowsum) {
    extern __shared__ float sm[];
    float* Qs  = sm;            // [q][d]   64x64
    float* KsT = sm + 4096;     // [d][key] 64x64
    float* Vs  = sm + 8192;     // [key][dv]
    float* Ss  = sm + 12288;    // [q][key]
    float* rs  = sm + 16384;    // [64]

    int qt = blockIdx.x, h = blockIdx.y, b = blockIdx.z;
    int bh = b * H_ + h;
    int tid = threadIdx.x, tx = tid & 15, ty = tid >> 4;

    const float4* Qg = (const float4*)(Q + ((size_t)bh * L_ + qt * 64) * DK_);
    #pragma unroll
    for (int i = 0; i < 4; i++) ((float4*)Qs)[tid + i * 256] = Qg[tid + i * 256];
    if (tid < 64) rs[tid] = 0.f;

    float accO[4][4];
    #pragma unroll
    for (int i = 0; i < 4; i++)
        #pragma unroll
        for (int j = 0; j < 4; j++) accO[i][j] = 0.f;

    const int* mrow = mask + b * L_;

    for (int kt = 0; kt < 32; kt++) {
        const float4* Kg = (const float4*)(K + ((size_t)bh * L_ + kt * 64) * DK_);
        const float4* Vg = (const float4*)(V + ((size_t)bh * L_ + kt * 64) * DK_);
        __syncthreads();
        #pragma unroll
        for (int i = 0; i < 4; i++) {
            int e = tid + i * 256;
            int r = e >> 4, c = (e & 15) * 4;
            float4 kv = Kg[e];
            KsT[(c + 0) * 64 + r] = kv.x;
            KsT[(c + 1) * 64 + r] = kv.y;
            KsT[(c + 2) * 64 + r] = kv.z;
            KsT[(c + 3) * 64 + r] = kv.w;
            ((float4*)Vs)[e] = Vg[e];
        }
        __syncthreads();

        float acc[4][4];
        #pragma unroll
        for (int i = 0; i < 4; i++)
            #pragma unroll
            for (int j = 0; j < 4; j++) acc[i][j] = 0.f;

        #pragma unroll
        for (int d4 = 0; d4 < 16; d4++) {
            float4 qv[4], kb[4];
            #pragma unroll
            for (int i = 0; i < 4; i++)
                qv[i] = *(const float4*)(Qs + (ty * 4 + i) * 64 + d4 * 4);
            #pragma unroll
            for (int dd = 0; dd < 4; dd++)
                kb[dd] = *(const float4*)(KsT + (d4 * 4 + dd) * 64 + tx * 4);
            const float* qf = (const float*)qv;
            const float* kf = (const float*)kb;
            #pragma unroll
            for (int i = 0; i < 4; i++)
                #pragma unroll
                for (int j = 0; j < 4; j++)
                    #pragma unroll
                    for (int dd = 0; dd < 4; dd++)
                        acc[i][j] = fmaf(qf[i * 4 + dd], kf[dd * 4 + j], acc[i][j]);
        }

        // prior * mask * exp, write unnormalized attn, rowsums, stage to Ss
        int kbase = kt * 64 + tx * 4;
        int4 mk = *(const int4*)(mrow + kbase);
        #pragma unroll
        for (int i = 0; i < 4; i++) {
            int qg = qt * 64 + ty * 4 + i;
            float4 pr = *(const float4*)(prior + ((size_t)b * L_ + qg) * L_ + kbase);
            float s0 = acc[i][0] * 0.125f * pr.x; if (mk.x == 0) s0 = -1e9f;
            float s1 = acc[i][1] * 0.125f * pr.y; if (mk.y == 0) s1 = -1e9f;
            float s2 = acc[i][2] * 0.125f * pr.z; if (mk.z == 0) s2 = -1e9f;
            float s3 = acc[i][3] * 0.125f * pr.w; if (mk.w == 0) s3 = -1e9f;
            float4 e4 = make_float4(__expf(s0), __expf(s1), __expf(s2), __expf(s3));
            *(float4*)(Ss + (ty * 4 + i) * 64 + tx * 4) = e4;
            *(float4*)(attn + ((size_t)bh * L_ + qg) * L_ + kbase) = e4;
            float vsum = e4.x + e4.y + e4.z + e4.w;
            vsum += __shfl_xor_sync(0xffffffffu, vsum, 1);
            vsum += __shfl_xor_sync(0xffffffffu, vsum, 2);
            vsum += __shfl_xor_sync(0xffffffffu, vsum, 4);
            vsum += __shfl_xor_sync(0xffffffffu, vsum, 8);
            if (tx == 0) rs[ty * 4 + i] += vsum;
        }
        __syncthreads();

        // O += e @ V
        #pragma unroll
        for (int k4 = 0; k4 < 16; k4++) {
            float4 ev[4], vv[4];
            #pragma unroll
            for (int i = 0; i < 4; i++)
                ev[i] = *(const float4*)(Ss + (ty * 4 + i) * 64 + k4 * 4);
            #pragma unroll
            for (int kk = 0; kk < 4; kk++)
                vv[kk] = *(const float4*)(Vs + (k4 * 4 + kk) * 64 + tx * 4);
            const float* ef = (const float*)ev;
            const float* vf = (const float*)vv;
            #pragma unroll
            for (int i = 0; i < 4; i++)
                #pragma unroll
                for (int j = 0; j < 4; j++)
                    #pragma unroll
                    for (int kk = 0; kk < 4; kk++)
                        accO[i][j] = fmaf(ef[i * 4 + kk], vf[kk * 4 + j], accO[i][j]);
        }
    }
    __syncthreads();

    #pragma unroll
    for (int i = 0; i < 4; i++) {
        int q = ty * 4 + i;
        float inv = 1.0f / rs[q];
        int lg = qt * 64 + q;
        float4 o4 = make_float4(accO[i][0] * inv, accO[i][1] * inv,
                                accO[i][2] * inv, accO[i][3] * inv);
        *(float4*)(O + ((size_t)b * L_ + lg) * D_ + h * 64 + tx * 4) = o4;
    }
    if (tid < 64) rowsum[(size_t)bh * L_ + qt * 64 + tid] = rs[tid];
}

// ---------------- normalize attn rows by their softmax sums ----------------
__global__ __launch_bounds__(256) void attn_norm(float* __restrict__ attn,
                                                 const float* __restrict__ rowsum) {
    int row = blockIdx.x;  // [0, BH_*L_)
    float inv = 1.0f / __ldg(rowsum + row);
    float4* p = (float4*)(attn + (size_t)row * L_);
    float4 a = p[threadIdx.x];
    a.x *= inv; a.y *= inv; a.z *= inv; a.w *= inv;
    p[threadIdx.x] = a;
    float4 c = p[threadIdx.x + 256];
    c.x *= inv; c.y *= inv; c.z *= inv; c.w *= inv;
    p[threadIdx.x + 256] = c;
}

// ---------------- host launcher ----------------
extern "C" void kernel_launch(void* const* d_in, const int* in_sizes, int n_in,
                              void* d_out, int out_size) {
    const float* src   = (const float*)d_in[0];
    const int*   mask  = (const int*)d_in[1];
    const float* prior = (const float*)d_in[2];
    const float* ln1_g = (const float*)d_in[3];
    const float* ln1_b = (const float*)d_in[4];
    const float* wq    = (const float*)d_in[5];
    const float* wk    = (const float*)d_in[6];
    const float* wv    = (const float*)d_in[7];
    const float* fc_w  = (const float*)d_in[8];
    const float* ln2_g = (const float*)d_in[9];
    const float* ln2_b = (const float*)d_in[10];
    const float* w1_w  = (const float*)d_in[11];
    const float* w1_b  = (const float*)d_in[12];
    const float* w2_w  = (const float*)d_in[13];
    const float* w2_b  = (const float*)d_in[14];

    float* out      = (float*)d_out;
    float* y_out    = out;                       // [B,L,D]
    float* attn_out = out + (size_t)M_ * D_;     // [B,H,L,L]

    float *x, *q, *k, *v, *o, *y, *z, *hb, *rsum;
    cudaGetSymbolAddress((void**)&x,    g_x);
    cudaGetSymbolAddress((void**)&q,    g_q);
    cudaGetSymbolAddress((void**)&k,    g_k);
    cudaGetSymbolAddress((void**)&v,    g_v);
    cudaGetSymbolAddress((void**)&o,    g_o);
    cudaGetSymbolAddress((void**)&y,    g_y);
    cudaGetSymbolAddress((void**)&z,    g_z);
    cudaGetSymbolAddress((void**)&hb,   g_h);
    cudaGetSymbolAddress((void**)&rsum, g_rowsum);

    const int attn_smem = (4 * 4096 + 64) * 4;
    cudaFuncSetAttribute(attn_kernel, cudaFuncAttributeMaxDynamicSharedMemorySize, attn_smem);

    // 1) LN1
    ln_kernel<<<M_, 256>>>(src, ln1_g, ln1_b, x);

    // 2) QKV projections (NT GEMM, permuted write into [b,h,l,d])
    dim3 gqkv(D_ / 128, M_ / 128);
    gemm_nt<EPI_QKV><<<gqkv, 256>>>(x, wq, q, nullptr, nullptr, M_, D_, D_);
    gemm_nt<EPI_QKV><<<gqkv, 256>>>(x, wk, k, nullptr, nullptr, M_, D_, D_);
    gemm_nt<EPI_QKV><<<gqkv, 256>>>(x, wv, v, nullptr, nullptr, M_, D_, D_);

    // 3) fused attention
    dim3 gattn(L_ / 64, H_, B_);
    attn_kernel<<<gattn, 256, attn_smem>>>(q, k, v, prior, mask, attn_out, o, rsum);

    // 4) normalize attn output rows
    attn_norm<<<BH_ * L_, 256>>>(attn_out, rsum);

    // 5) fc + residual
    gemm_nt<EPI_RES><<<dim3(D_ / 128, M_ / 128), 256>>>(o, fc_w, y, nullptr, src, M_, D_, D_);

    // 6) LN2
    ln_kernel<<<M_, 256>>>(y, ln2_g, ln2_b, z);

    // 7) FFN up + ReLU
    gemm_nt<EPI_BIAS_RELU><<<dim3(DFF_ / 128, M_ / 128), 256>>>(z, w1_w, hb, w1_b, nullptr, M_, DFF_, D_);

    // 8) FFN down + bias + residual -> final y in d_out
    gemm_nt<EPI_BIAS_RES><<<dim3(D_ / 128, M_ / 128), 256>>>(hb, w2_w, y_out, w2_b, y, M_, D_, DFF_);
}

// round 3
// speedup vs baseline: 1.8956x; 1.8956x over previous
#include <cuda_runtime.h>
#include <cuda_bf16.h>
#include <stdint.h>
#include <math.h>

#define B_   4
#define L_   2048
#define D_   1024
#define H_   16
#define DK_  64
#define DFF_ 4096
#define M_   (B_*L_)    // 8192 rows
#define BH_  (B_*H_)    // 64
#define QKVN (3*D_)     // 3072

// ---------------- scratch (static device globals; no allocation) ----------------
__device__ __nv_bfloat16 g_xh[M_*D_],  g_xl[M_*D_];    // LN1 out split
__device__ __nv_bfloat16 g_zh[M_*D_],  g_zl[M_*D_];    // LN2 out split
__device__ __nv_bfloat16 g_oh[M_*D_],  g_ol[M_*D_];    // attn O split
__device__ __nv_bfloat16 g_hh[M_*DFF_],g_hl[M_*DFF_];  // FFN hidden split
__device__ float g_qkv[3*BH_*L_*DK_];                  // q,k,v packed
__device__ float g_y[M_*D_];
__device__ float g_rowsum[BH_*L_];
// weight splits (qkv combined: rows 0..1023=Q, 1024..2047=K, 2048..3071=V)
__device__ __nv_bfloat16 g_wqkvh[QKVN*D_], g_wqkvl[QKVN*D_];
__device__ __nv_bfloat16 g_fch[D_*H_*DK_], g_fcl[D_*H_*DK_];
__device__ __nv_bfloat16 g_w1h[DFF_*D_],   g_w1l[DFF_*D_];
__device__ __nv_bfloat16 g_w2h[D_*DFF_],   g_w2l[D_*DFF_];

// ---------------- small PTX helpers ----------------
static __device__ __forceinline__ uint32_t s2u(const void* p) {
    uint32_t a;
    asm("{ .reg .u64 t; cvta.to.shared.u64 t, %1; cvt.u32.u64 %0, t; }" : "=r"(a) : "l"(p));
    return a;
}
static __device__ __forceinline__ void cp16(uint32_t dst, const void* src) {
    asm volatile("cp.async.cg.shared.global [%0], [%1], 16;" :: "r"(dst), "l"(src) : "memory");
}
static __device__ __forceinline__ void cp_commit() { asm volatile("cp.async.commit_group;" ::: "memory"); }
static __device__ __forceinline__ void cp_wait1()  { asm volatile("cp.async.wait_group 1;" ::: "memory"); }
static __device__ __forceinline__ void cp_wait0()  { asm volatile("cp.async.wait_group 0;" ::: "memory"); }

static __device__ __forceinline__ void ldsm_x4(uint32_t* r, uint32_t addr) {
    asm volatile("ldmatrix.sync.aligned.m8n8.x4.shared.b16 {%0,%1,%2,%3}, [%4];"
                 : "=r"(r[0]), "=r"(r[1]), "=r"(r[2]), "=r"(r[3]) : "r"(addr));
}
static __device__ __forceinline__ void ldsm_x2(uint32_t* r, uint32_t addr) {
    asm volatile("ldmatrix.sync.aligned.m8n8.x2.shared.b16 {%0,%1}, [%2];"
                 : "=r"(r[0]), "=r"(r[1]) : "r"(addr));
}
static __device__ __forceinline__ void mma16816(float* d, const uint32_t* a, const uint32_t* b) {
    asm volatile("mma.sync.aligned.m16n8k16.row.col.f32.bf16.bf16.f32 "
                 "{%0,%1,%2,%3}, {%4,%5,%6,%7}, {%8,%9}, {%0,%1,%2,%3};"
                 : "+f"(d[0]), "+f"(d[1]), "+f"(d[2]), "+f"(d[3])
                 : "r"(a[0]), "r"(a[1]), "r"(a[2]), "r"(a[3]), "r"(b[0]), "r"(b[1]));
}

// split floats -> hi/lo bf16
static __device__ __forceinline__ void split_store4(__nv_bfloat16* __restrict__ Hp,
                                                    __nv_bfloat16* __restrict__ Lp,
                                                    size_t idx, float4 v) {
    __nv_bfloat16 h0 = __float2bfloat16(v.x), h1 = __float2bfloat16(v.y);
    __nv_bfloat16 h2 = __float2bfloat16(v.z), h3 = __float2bfloat16(v.w);
    float l0 = v.x - __bfloat162float(h0), l1 = v.y - __bfloat162float(h1);
    float l2 = v.z - __bfloat162float(h2), l3 = v.w - __bfloat162float(h3);
    __nv_bfloat162 hp0 = __halves2bfloat162(h0, h1), hp1 = __halves2bfloat162(h2, h3);
    __nv_bfloat162 lp0 = __floats2bfloat162_rn(l0, l1), lp1 = __floats2bfloat162_rn(l2, l3);
    uint2 hu = make_uint2(*(uint32_t*)&hp0, *(uint32_t*)&hp1);
    uint2 lu = make_uint2(*(uint32_t*)&lp0, *(uint32_t*)&lp1);
    *(uint2*)(Hp + idx) = hu;
    *(uint2*)(Lp + idx) = lu;
}
static __device__ __forceinline__ void split_store2(__nv_bfloat16* __restrict__ Hp,
                                                    __nv_bfloat16* __restrict__ Lp,
                                                    size_t idx, float a, float b) {
    __nv_bfloat16 h0 = __float2bfloat16(a), h1 = __float2bfloat16(b);
    float l0 = a - __bfloat162float(h0), l1 = b - __bfloat162float(h1);
    __nv_bfloat162 hp = __halves2bfloat162(h0, h1);
    __nv_bfloat162 lp = __floats2bfloat162_rn(l0, l1);
    *(uint32_t*)(Hp + idx) = *(uint32_t*)&hp;
    *(uint32_t*)(Lp + idx) = *(uint32_t*)&lp;
}

// ---------------- weight split: fp32 -> bf16 hi/lo ----------------
__global__ __launch_bounds__(256) void split_kernel(const float* __restrict__ in,
                                                    __nv_bfloat16* __restrict__ Hp,
                                                    __nv_bfloat16* __restrict__ Lp,
                                                    int n4) {
    int i = blockIdx.x * 256 + threadIdx.x;
    if (i < n4) {
        float4 v = ((const float4*)in)[i];
        split_store4(Hp, Lp, (size_t)i * 4, v);
    }
}

// ---------------- LayerNorm -> bf16 hi/lo ----------------
__global__ __launch_bounds__(256) void ln_kernel(const float* __restrict__ in,
                                                 const float* __restrict__ g,
                                                 const float* __restrict__ b,
                                                 __nv_bfloat16* __restrict__ outH,
                                                 __nv_bfloat16* __restrict__ outL) {
    int row = blockIdx.x;
    const float4* inr = (const float4*)(in + (size_t)row * D_);
    float4 v = inr[threadIdx.x];
    float s  = v.x + v.y + v.z + v.w;
    float ss = v.x*v.x + v.y*v.y + v.z*v.z + v.w*v.w;
    #pragma unroll
    for (int o = 16; o > 0; o >>= 1) {
        s  += __shfl_xor_sync(0xffffffffu, s,  o);
        ss += __shfl_xor_sync(0xffffffffu, ss, o);
    }
    __shared__ float red[16];
    __shared__ float mv[2];
    int w = threadIdx.x >> 5, ln = threadIdx.x & 31;
    if (ln == 0) { red[w] = s; red[w + 8] = ss; }
    __syncthreads();
    if (threadIdx.x == 0) {
        float a = 0.f, q = 0.f;
        #pragma unroll
        for (int i = 0; i < 8; i++) { a += red[i]; q += red[i + 8]; }
        float mu = a * (1.0f / D_);
        mv[0] = mu;
        mv[1] = rsqrtf(q * (1.0f / D_) - mu * mu + 1e-6f);
    }
    __syncthreads();
    float mu = mv[0], rs = mv[1];
    float4 gg = ((const float4*)g)[threadIdx.x];
    float4 bb = ((const float4*)b)[threadIdx.x];
    float4 o4;
    o4.x = (v.x - mu) * rs * gg.x + bb.x;
    o4.y = (v.y - mu) * rs * gg.y + bb.y;
    o4.z = (v.z - mu) * rs * gg.z + bb.z;
    o4.w = (v.w - mu) * rs * gg.w + bb.w;
    split_store4(outH, outL, (size_t)row * D_ + threadIdx.x * 4, o4);
}

// ---------------- HMMA bf16x3 NT GEMM ----------------
// C[m,n] = sum_k A[m,k]*B[n,k] via Ah*Bh + Ah*Bl + Al*Bh, fp32 reg accum.
// CTA 128x128, K-chunk 64, 2-stage cp.async, 8 warps (2m x 4n), warp tile 64x32.
enum { EPI_QKV = 0, EPI_RES = 1, EPI_BIAS_RELU = 2, EPI_BIAS_RES = 3 };

static __device__ __forceinline__ void load_chunk(uint32_t stage,
    const __nv_bfloat16* __restrict__ Ah, const __nv_bfloat16* __restrict__ Al,
    const __nv_bfloat16* __restrict__ Bh, const __nv_bfloat16* __restrict__ Bl,
    int bm, int bn, int kc, int K, int tid)
{
    #pragma unroll
    for (int it = 0; it < 4; it++) {
        int e = tid + it * 256;        // 0..1023
        int row = e >> 3, seg = e & 7;
        uint32_t off = (uint32_t)(row * 128 + seg * 16);
        uint32_t sw  = off ^ ((off >> 3) & 0x70u);
        size_t ga = (size_t)(bm + row) * K + (size_t)kc * 64 + seg * 8;
        size_t gb = (size_t)(bn + row) * K + (size_t)kc * 64 + seg * 8;
        cp16(stage +     0u + sw, Ah + ga);
        cp16(stage + 16384u + sw, Al + ga);
        cp16(stage + 32768u + sw, Bh + gb);
        cp16(stage + 49152u + sw, Bl + gb);
    }
}

template <int EPI>
__global__ __launch_bounds__(256)
void mm_hmma(const __nv_bfloat16* __restrict__ Ah, const __nv_bfloat16* __restrict__ Al,
             const __nv_bfloat16* __restrict__ Bh, const __nv_bfloat16* __restrict__ Bl,
             float* __restrict__ outF,
             __nv_bfloat16* __restrict__ outH, __nv_bfloat16* __restrict__ outL,
             const float* __restrict__ bias, const float* __restrict__ res,
             int M, int N, int K)
{
    extern __shared__ char smem[];
    uint32_t tiles = s2u(smem);
    int tid = threadIdx.x, wid = tid >> 5, lane = tid & 31;
    int bm = blockIdx.y * 128, bn = blockIdx.x * 128;
    int wm = wid & 1, wn = wid >> 1;       // warp 64m x 32n tile
    int g = lane >> 3, lr = lane & 7;

    float acc[4][4][4];
    #pragma unroll
    for (int mt = 0; mt < 4; mt++)
        #pragma unroll
        for (int nt = 0; nt < 4; nt++)
            #pragma unroll
            for (int j = 0; j < 4; j++) acc[mt][nt][j] = 0.f;

    const int nc = K >> 6;
    load_chunk(tiles, Ah, Al, Bh, Bl, bm, bn, 0, K, tid);
    cp_commit();

    for (int i = 0; i < nc; i++) {
        if (i > 0) __syncthreads();    // stage (i+1)&1 about to be overwritten
        if (i + 1 < nc) {
            load_chunk(tiles + (uint32_t)((i + 1) & 1) * 65536u, Ah, Al, Bh, Bl, bm, bn, i + 1, K, tid);
            cp_commit();
            cp_wait1();
        } else {
            cp_wait0();
        }
        __syncthreads();
        uint32_t st = tiles + (uint32_t)(i & 1) * 65536u;
        uint32_t stAh = st, stAl = st + 16384u, stBh = st + 32768u, stBl = st + 49152u;

        #pragma unroll
        for (int ks = 0; ks < 4; ks++) {
            uint32_t ah[4][4], al[4][4], bh[4][2], bl[4][2];
            int ka = ks * 32 + (g >> 1) * 16;   // byte offset of k for A ldsm
            int kb = ks * 32 + (g & 1) * 16;    // byte offset of k for B ldsm
            #pragma unroll
            for (int mt = 0; mt < 4; mt++) {
                int arow = wm * 64 + mt * 16 + (g & 1) * 8 + lr;
                uint32_t ao = (uint32_t)(arow * 128) + ((uint32_t)ka ^ (uint32_t)((arow & 7) << 4));
                ldsm_x4(ah[mt], stAh + ao);
                ldsm_x4(al[mt], stAl + ao);
            }
            #pragma unroll
            for (int nt = 0; nt < 4; nt++) {
                int brow = wn * 32 + nt * 8 + lr;
                uint32_t bo = (uint32_t)(brow * 128) + ((uint32_t)kb ^ (uint32_t)((brow & 7) << 4));
                ldsm_x2(bh[nt], stBh + bo);
                ldsm_x2(bl[nt], stBl + bo);
            }
            #pragma unroll
            for (int mt = 0; mt < 4; mt++)
                #pragma unroll
                for (int nt = 0; nt < 4; nt++) {
                    mma16816(acc[mt][nt], ah[mt], bh[nt]);
                    mma16816(acc[mt][nt], ah[mt], bl[nt]);
                    mma16816(acc[mt][nt], al[mt], bh[nt]);
                }
        }
    }

    // epilogue from register fragments:
    // thread holds C rows (r, r+8), cols (2c, 2c+1) of each 16x8 tile
    int r = lane >> 2, c = lane & 3;
    #pragma unroll
    for (int mt = 0; mt < 4; mt++) {
        int m0 = bm + wm * 64 + mt * 16 + r;
        #pragma unroll
        for (int nt = 0; nt < 4; nt++) {
            int n = bn + wn * 32 + nt * 8 + c * 2;
            float d0 = acc[mt][nt][0], d1 = acc[mt][nt][1];
            float d2 = acc[mt][nt][2], d3 = acc[mt][nt][3];
            if (EPI == EPI_QKV) {
                int mat = n >> 10, nn = n & 1023;
                int bb = m0 >> 11, l = m0 & 2047, hh = nn >> 6, dd = nn & 63;
                float* dst = outF + (size_t)mat * (BH_*L_*DK_)
                           + (((size_t)(bb * H_ + hh) * L_ + l) * DK_ + dd);
                *(float2*)dst            = make_float2(d0, d1);
                *(float2*)(dst + 8*DK_)  = make_float2(d2, d3);
            } else if (EPI == EPI_RES) {
                size_t off = (size_t)m0 * N + n;
                float2 r0 = *(const float2*)(res + off);
                float2 r1 = *(const float2*)(res + off + 8*(size_t)N);
                *(float2*)(outF + off)              = make_float2(d0 + r0.x, d1 + r0.y);
                *(float2*)(outF + off + 8*(size_t)N)= make_float2(d2 + r1.x, d3 + r1.y);
            } else if (EPI == EPI_BIAS_RELU) {
                size_t off = (size_t)m0 * N + n;
                float2 bv = *(const float2*)(bias + n);
                split_store2(outH, outL, off,
                             fmaxf(d0 + bv.x, 0.f), fmaxf(d1 + bv.y, 0.f));
                split_store2(outH, outL, off + 8*(size_t)N,
                             fmaxf(d2 + bv.x, 0.f), fmaxf(d3 + bv.y, 0.f));
            } else { // EPI_BIAS_RES
                size_t off = (size_t)m0 * N + n;
                float2 bv = *(const float2*)(bias + n);
                float2 r0 = *(const float2*)(res + off);
                float2 r1 = *(const float2*)(res + off + 8*(size_t)N);
                *(float2*)(outF + off)               = make_float2(d0 + bv.x + r0.x, d1 + bv.y + r0.y);
                *(float2*)(outF + off + 8*(size_t)N) = make_float2(d2 + bv.x + r1.x, d3 + bv.y + r1.y);
            }
        }
    }
}

// ---------------- Fused attention (SIMT); O written as bf16 hi/lo ----------------
__global__ __launch_bounds__(256) void attn_kernel(const float* __restrict__ Q,
                                                   const float* __restrict__ K,
                                                   const float* __restrict__ V,
                                                   const float* __restrict__ prior,
                                                   const int* __restrict__ mask,
                                                   float* __restrict__ attn,
                                                   __nv_bfloat16* __restrict__ Oh,
                                                   __nv_bfloat16* __restrict__ Ol,
                                                   float* __restrict__ rowsum) {
    extern __shared__ float sm[];
    float* Qs  = sm;            // [q][d]   64x64
    float* KsT = sm + 4096;     // [d][key] 64x64
    float* Vs  = sm + 8192;     // [key][dv]
    float* Ss  = sm + 12288;    // [q][key]
    float* rs  = sm + 16384;    // [64]

    int qt = blockIdx.x, h = blockIdx.y, b = blockIdx.z;
    int bh = b * H_ + h;
    int tid = threadIdx.x, tx = tid & 15, ty = tid >> 4;

    const float4* Qg = (const float4*)(Q + ((size_t)bh * L_ + qt * 64) * DK_);
    #pragma unroll
    for (int i = 0; i < 4; i++) ((float4*)Qs)[tid + i * 256] = Qg[tid + i * 256];
    if (tid < 64) rs[tid] = 0.f;

    float accO[4][4];
    #pragma unroll
    for (int i = 0; i < 4; i++)
        #pragma unroll
        for (int j = 0; j < 4; j++) accO[i][j] = 0.f;

    const int* mrow = mask + b * L_;

    for (int kt = 0; kt < 32; kt++) {
        const float4* Kg = (const float4*)(K + ((size_t)bh * L_ + kt * 64) * DK_);
        const float4* Vg = (const float4*)(V + ((size_t)bh * L_ + kt * 64) * DK_);
        __syncthreads();
        #pragma unroll
        for (int i = 0; i < 4; i++) {
            int e = tid + i * 256;
            int r = e >> 4, c = (e & 15) * 4;
            float4 kv = Kg[e];
            KsT[(c + 0) * 64 + r] = kv.x;
            KsT[(c + 1) * 64 + r] = kv.y;
            KsT[(c + 2) * 64 + r] = kv.z;
            KsT[(c + 3) * 64 + r] = kv.w;
            ((float4*)Vs)[e] = Vg[e];
        }
        __syncthreads();

        float acc[4][4];
        #pragma unroll
        for (int i = 0; i < 4; i++)
            #pragma unroll
            for (int j = 0; j < 4; j++) acc[i][j] = 0.f;

        #pragma unroll
        for (int d4 = 0; d4 < 16; d4++) {
            float4 qv[4], kb[4];
            #pragma unroll
            for (int i = 0; i < 4; i++)
                qv[i] = *(const float4*)(Qs + (ty * 4 + i) * 64 + d4 * 4);
            #pragma unroll
            for (int dd = 0; dd < 4; dd++)
                kb[dd] = *(const float4*)(KsT + (d4 * 4 + dd) * 64 + tx * 4);
            const float* qf = (const float*)qv;
            const float* kf = (const float*)kb;
            #pragma unroll
            for (int i = 0; i < 4; i++)
                #pragma unroll
                for (int j = 0; j < 4; j++)
                    #pragma unroll
                    for (int dd = 0; dd < 4; dd++)
                        acc[i][j] = fmaf(qf[i * 4 + dd], kf[dd * 4 + j], acc[i][j]);
        }

        int kbase = kt * 64 + tx * 4;
        int4 mk = *(const int4*)(mrow + kbase);
        #pragma unroll
        for (int i = 0; i < 4; i++) {
            int qg = qt * 64 + ty * 4 + i;
            float4 pr = *(const float4*)(prior + ((size_t)b * L_ + qg) * L_ + kbase);
            float s0 = acc[i][0] * 0.125f * pr.x; if (mk.x == 0) s0 = -1e9f;
            float s1 = acc[i][1] * 0.125f * pr.y; if (mk.y == 0) s1 = -1e9f;
            float s2 = acc[i][2] * 0.125f * pr.z; if (mk.z == 0) s2 = -1e9f;
            float s3 = acc[i][3] * 0.125f * pr.w; if (mk.w == 0) s3 = -1e9f;
            float4 e4 = make_float4(__expf(s0), __expf(s1), __expf(s2), __expf(s3));
            *(float4*)(Ss + (ty * 4 + i) * 64 + tx * 4) = e4;
            *(float4*)(attn + ((size_t)bh * L_ + qg) * L_ + kbase) = e4;
            float vsum = e4.x + e4.y + e4.z + e4.w;
            vsum += __shfl_xor_sync(0xffffffffu, vsum, 1);
            vsum += __shfl_xor_sync(0xffffffffu, vsum, 2);
            vsum += __shfl_xor_sync(0xffffffffu, vsum, 4);
            vsum += __shfl_xor_sync(0xffffffffu, vsum, 8);
            if (tx == 0) rs[ty * 4 + i] += vsum;
        }
        __syncthreads();

        #pragma unroll
        for (int k4 = 0; k4 < 16; k4++) {
            float4 ev[4], vv[4];
            #pragma unroll
            for (int i = 0; i < 4; i++)
                ev[i] = *(const float4*)(Ss + (ty * 4 + i) * 64 + k4 * 4);
            #pragma unroll
            for (int kk = 0; kk < 4; kk++)
                vv[kk] = *(const float4*)(Vs + (k4 * 4 + kk) * 64 + tx * 4);
            const float* ef = (const float*)ev;
            const float* vf = (const float*)vv;
            #pragma unroll
            for (int i = 0; i < 4; i++)
                #pragma unroll
                for (int j = 0; j < 4; j++)
                    #pragma unroll
                    for (int kk = 0; kk < 4; kk++)
                        accO[i][j] = fmaf(ef[i * 4 + kk], vf[kk * 4 + j], accO[i][j]);
        }
    }
    __syncthreads();

    #pragma unroll
    for (int i = 0; i < 4; i++) {
        int q = ty * 4 + i;
        float inv = 1.0f / rs[q];
        int lg = qt * 64 + q;
        float4 o4 = make_float4(accO[i][0] * inv, accO[i][1] * inv,
                                accO[i][2] * inv, accO[i][3] * inv);
        size_t oidx = ((size_t)b * L_ + lg) * D_ + h * 64 + tx * 4;
        split_store4(Oh, Ol, oidx, o4);
    }
    if (tid < 64) rowsum[(size_t)bh * L_ + qt * 64 + tid] = rs[tid];
}

// ---------------- normalize attn rows ----------------
__global__ __launch_bounds__(256) void attn_norm(float* __restrict__ attn,
                                                 const float* __restrict__ rowsum) {
    int row = blockIdx.x;
    float inv = 1.0f / __ldg(rowsum + row);
    float4* p = (float4*)(attn + (size_t)row * L_);
    float4 a = p[threadIdx.x];
    a.x *= inv; a.y *= inv; a.z *= inv; a.w *= inv;
    p[threadIdx.x] = a;
    float4 c = p[threadIdx.x + 256];
    c.x *= inv; c.y *= inv; c.z *= inv; c.w *= inv;
    p[threadIdx.x + 256] = c;
}

// ---------------- host launcher ----------------
extern "C" void kernel_launch(void* const* d_in, const int* in_sizes, int n_in,
                              void* d_out, int out_size) {
    const float* src   = (const float*)d_in[0];
    const int*   mask  = (const int*)d_in[1];
    const float* prior = (const float*)d_in[2];
    const float* ln1_g = (const float*)d_in[3];
    const float* ln1_b = (const float*)d_in[4];
    const float* wq    = (const float*)d_in[5];
    const float* wk    = (const float*)d_in[6];
    const float* wv    = (const float*)d_in[7];
    const float* fc_w  = (const float*)d_in[8];
    const float* ln2_g = (const float*)d_in[9];
    const float* ln2_b = (const float*)d_in[10];
    const float* w1_w  = (const float*)d_in[11];
    const float* w1_b  = (const float*)d_in[12];
    const float* w2_w  = (const float*)d_in[13];
    const float* w2_b  = (const float*)d_in[14];

    float* out      = (float*)d_out;
    float* y_out    = out;                       // [B,L,D]
    float* attn_out = out + (size_t)M_ * D_;     // [B,H,L,L]

    __nv_bfloat16 *xh, *xl, *zh, *zl, *oh, *ol, *hh, *hl;
    __nv_bfloat16 *wqkvh, *wqkvl, *fch, *fcl, *w1h, *w1l, *w2h, *w2l;
    float *qkv, *y, *rsum;
    cudaGetSymbolAddress((void**)&xh, g_xh);  cudaGetSymbolAddress((void**)&xl, g_xl);
    cudaGetSymbolAddress((void**)&zh, g_zh);  cudaGetSymbolAddress((void**)&zl, g_zl);
    cudaGetSymbolAddress((void**)&oh, g_oh);  cudaGetSymbolAddress((void**)&ol, g_ol);
    cudaGetSymbolAddress((void**)&hh, g_hh);  cudaGetSymbolAddress((void**)&hl, g_hl);
    cudaGetSymbolAddress((void**)&wqkvh, g_wqkvh); cudaGetSymbolAddress((void**)&wqkvl, g_wqkvl);
    cudaGetSymbolAddress((void**)&fch, g_fch); cudaGetSymbolAddress((void**)&fcl, g_fcl);
    cudaGetSymbolAddress((void**)&w1h, g_w1h); cudaGetSymbolAddress((void**)&w1l, g_w1l);
    cudaGetSymbolAddress((void**)&w2h, g_w2h); cudaGetSymbolAddress((void**)&w2l, g_w2l);
    cudaGetSymbolAddress((void**)&qkv, g_qkv);
    cudaGetSymbolAddress((void**)&y, g_y);
    cudaGetSymbolAddress((void**)&rsum, g_rowsum);

    const int attn_smem = (4 * 4096 + 64) * 4;
    cudaFuncSetAttribute(attn_kernel, cudaFuncAttributeMaxDynamicSharedMemorySize, attn_smem);
    const int mm_smem = 2 * 65536;
    cudaFuncSetAttribute(mm_hmma<EPI_QKV>,       cudaFuncAttributeMaxDynamicSharedMemorySize, mm_smem);
    cudaFuncSetAttribute(mm_hmma<EPI_RES>,       cudaFuncAttributeMaxDynamicSharedMemorySize, mm_smem);
    cudaFuncSetAttribute(mm_hmma<EPI_BIAS_RELU>, cudaFuncAttributeMaxDynamicSharedMemorySize, mm_smem);
    cudaFuncSetAttribute(mm_hmma<EPI_BIAS_RES>,  cudaFuncAttributeMaxDynamicSharedMemorySize, mm_smem);

    // 0) split weights to bf16 hi/lo (QKV concatenated)
    split_kernel<<<1024, 256>>>(wq,   wqkvh,                wqkvl,                (D_*D_) / 4);
    split_kernel<<<1024, 256>>>(wk,   wqkvh + (size_t)D_*D_, wqkvl + (size_t)D_*D_, (D_*D_) / 4);
    split_kernel<<<1024, 256>>>(wv,   wqkvh + 2*(size_t)D_*D_, wqkvl + 2*(size_t)D_*D_, (D_*D_) / 4);
    split_kernel<<<1024, 256>>>(fc_w, fch, fcl, (D_*H_*DK_) / 4);
    split_kernel<<<4096, 256>>>(w1_w, w1h, w1l, (DFF_*D_) / 4);
    split_kernel<<<4096, 256>>>(w2_w, w2h, w2l, (D_*DFF_) / 4);

    // 1) LN1 -> x split
    ln_kernel<<<M_, 256>>>(src, ln1_g, ln1_b, xh, xl);

    // 2) fused QKV projection (N=3072), scatter into packed [3][b,h,l,d]
    mm_hmma<EPI_QKV><<<dim3(QKVN / 128, M_ / 128), 256, mm_smem>>>(
        xh, xl, wqkvh, wqkvl, qkv, nullptr, nullptr, nullptr, nullptr, M_, QKVN, D_);

    const float* q = qkv;
    const float* k = qkv + (size_t)BH_*L_*DK_;
    const float* v = qkv + 2*(size_t)BH_*L_*DK_;

    // 3) fused attention (O written as bf16 split)
    dim3 gattn(L_ / 64, H_, B_);
    attn_kernel<<<gattn, 256, attn_smem>>>(q, k, v, prior, mask, attn_out, oh, ol, rsum);

    // 4) normalize attn rows
    attn_norm<<<BH_ * L_, 256>>>(attn_out, rsum);

    // 5) fc + residual -> y (fp32)
    mm_hmma<EPI_RES><<<dim3(D_ / 128, M_ / 128), 256, mm_smem>>>(
        oh, ol, fch, fcl, y, nullptr, nullptr, nullptr, src, M_, D_, D_);

    // 6) LN2 -> z split
    ln_kernel<<<M_, 256>>>(y, ln2_g, ln2_b, zh, zl);

    // 7) FFN up + ReLU -> h split (bf16)
    mm_hmma<EPI_BIAS_RELU><<<dim3(DFF_ / 128, M_ / 128), 256, mm_smem>>>(
        zh, zl, w1h, w1l, nullptr, hh, hl, w1_b, nullptr, M_, DFF_, D_);

    // 8) FFN down + bias + residual -> final y
    mm_hmma<EPI_BIAS_RES><<<dim3(D_ / 128, M_ / 128), 256, mm_smem>>>(
        hh, hl, w2h, w2l, y_out, nullptr, nullptr, w2_b, y, M_, D_, DFF_);
}

// round 4
// speedup vs baseline: 2.7857x; 1.4696x over previous
#include <cuda_runtime.h>
#include <cuda_bf16.h>
#include <stdint.h>
#include <math.h>

#define B_   4
#define L_   2048
#define D_   1024
#define H_   16
#define DK_  64
#define DFF_ 4096
#define M_   (B_*L_)    // 8192 rows
#define BH_  (B_*H_)    // 64
#define QKVN (3*D_)     // 3072
#define QT_  128        // q rows per attention CTA

// ---------------- scratch (static device globals; no allocation) ----------------
__device__ __nv_bfloat16 g_xh[M_*D_],  g_xl[M_*D_];    // LN1 out split
__device__ __nv_bfloat16 g_zh[M_*D_],  g_zl[M_*D_];    // LN2 out split
__device__ __nv_bfloat16 g_oh[M_*D_],  g_ol[M_*D_];    // attn O split
__device__ __nv_bfloat16 g_hh[M_*DFF_],g_hl[M_*DFF_];  // FFN hidden split
__device__ __nv_bfloat16 g_qkvh[3*(size_t)M_*D_], g_qkvl[3*(size_t)M_*D_]; // packed [3][b,h,l,dk]
__device__ float g_y[M_*D_];
__device__ float g_rowsum[BH_*L_];
// weight splits (qkv combined rows 0..1023=Q, 1024..2047=K, 2048..3071=V)
__device__ __nv_bfloat16 g_wqkvh[QKVN*D_], g_wqkvl[QKVN*D_];
__device__ __nv_bfloat16 g_fch[D_*H_*DK_], g_fcl[D_*H_*DK_];
__device__ __nv_bfloat16 g_w1h[DFF_*D_],   g_w1l[DFF_*D_];
__device__ __nv_bfloat16 g_w2h[D_*DFF_],   g_w2l[D_*DFF_];

// ---------------- small PTX helpers ----------------
static __device__ __forceinline__ uint32_t s2u(const void* p) {
    uint32_t a;
    asm("{ .reg .u64 t; cvta.to.shared.u64 t, %1; cvt.u32.u64 %0, t; }" : "=r"(a) : "l"(p));
    return a;
}
static __device__ __forceinline__ void cp16(uint32_t dst, const void* src) {
    asm volatile("cp.async.cg.shared.global [%0], [%1], 16;" :: "r"(dst), "l"(src) : "memory");
}
static __device__ __forceinline__ void cp_commit() { asm volatile("cp.async.commit_group;" ::: "memory"); }
static __device__ __forceinline__ void cp_wait1()  { asm volatile("cp.async.wait_group 1;" ::: "memory"); }
static __device__ __forceinline__ void cp_wait0()  { asm volatile("cp.async.wait_group 0;" ::: "memory"); }

static __device__ __forceinline__ void ldsm_x4(uint32_t* r, uint32_t addr) {
    asm volatile("ldmatrix.sync.aligned.m8n8.x4.shared.b16 {%0,%1,%2,%3}, [%4];"
                 : "=r"(r[0]), "=r"(r[1]), "=r"(r[2]), "=r"(r[3]) : "r"(addr));
}
static __device__ __forceinline__ void ldsm_x2(uint32_t* r, uint32_t addr) {
    asm volatile("ldmatrix.sync.aligned.m8n8.x2.shared.b16 {%0,%1}, [%2];"
                 : "=r"(r[0]), "=r"(r[1]) : "r"(addr));
}
static __device__ __forceinline__ void ldsm_x2t(uint32_t* r, uint32_t addr) {
    asm volatile("ldmatrix.sync.aligned.m8n8.x2.trans.shared.b16 {%0,%1}, [%2];"
                 : "=r"(r[0]), "=r"(r[1]) : "r"(addr));
}
static __device__ __forceinline__ void mma16816(float* d, const uint32_t* a, const uint32_t* b) {
    asm volatile("mma.sync.aligned.m16n8k16.row.col.f32.bf16.bf16.f32 "
                 "{%0,%1,%2,%3}, {%4,%5,%6,%7}, {%8,%9}, {%0,%1,%2,%3};"
                 : "+f"(d[0]), "+f"(d[1]), "+f"(d[2]), "+f"(d[3])
                 : "r"(a[0]), "r"(a[1]), "r"(a[2]), "r"(a[3]), "r"(b[0]), "r"(b[1]));
}

static __device__ __forceinline__ uint32_t pack_hi(float a, float b, float* la, float* lb) {
    __nv_bfloat16 h0 = __float2bfloat16(a), h1 = __float2bfloat16(b);
    *la = a - __bfloat162float(h0);
    *lb = b - __bfloat162float(h1);
    __nv_bfloat162 hp = __halves2bfloat162(h0, h1);
    return *(uint32_t*)&hp;
}
static __device__ __forceinline__ uint32_t pack_lo(float a, float b) {
    __nv_bfloat162 lp = __floats2bfloat162_rn(a, b);
    return *(uint32_t*)&lp;
}

// split floats -> hi/lo bf16 stores
static __device__ __forceinline__ void split_store4(__nv_bfloat16* __restrict__ Hp,
                                                    __nv_bfloat16* __restrict__ Lp,
                                                    size_t idx, float4 v) {
    __nv_bfloat16 h0 = __float2bfloat16(v.x), h1 = __float2bfloat16(v.y);
    __nv_bfloat16 h2 = __float2bfloat16(v.z), h3 = __float2bfloat16(v.w);
    float l0 = v.x - __bfloat162float(h0), l1 = v.y - __bfloat162float(h1);
    float l2 = v.z - __bfloat162float(h2), l3 = v.w - __bfloat162float(h3);
    __nv_bfloat162 hp0 = __halves2bfloat162(h0, h1), hp1 = __halves2bfloat162(h2, h3);
    __nv_bfloat162 lp0 = __floats2bfloat162_rn(l0, l1), lp1 = __floats2bfloat162_rn(l2, l3);
    uint2 hu = make_uint2(*(uint32_t*)&hp0, *(uint32_t*)&hp1);
    uint2 lu = make_uint2(*(uint32_t*)&lp0, *(uint32_t*)&lp1);
    *(uint2*)(Hp + idx) = hu;
    *(uint2*)(Lp + idx) = lu;
}
static __device__ __forceinline__ void split_store2(__nv_bfloat16* __restrict__ Hp,
                                                    __nv_bfloat16* __restrict__ Lp,
                                                    size_t idx, float a, float b) {
    __nv_bfloat16 h0 = __float2bfloat16(a), h1 = __float2bfloat16(b);
    float l0 = a - __bfloat162float(h0), l1 = b - __bfloat162float(h1);
    __nv_bfloat162 hp = __halves2bfloat162(h0, h1);
    __nv_bfloat162 lp = __floats2bfloat162_rn(l0, l1);
    *(uint32_t*)(Hp + idx) = *(uint32_t*)&hp;
    *(uint32_t*)(Lp + idx) = *(uint32_t*)&lp;
}

// ---------------- weight split: fp32 -> bf16 hi/lo ----------------
__global__ __launch_bounds__(256) void split_kernel(const float* __restrict__ in,
                                                    __nv_bfloat16* __restrict__ Hp,
                                                    __nv_bfloat16* __restrict__ Lp,
                                                    int n4) {
    int i = blockIdx.x * 256 + threadIdx.x;
    if (i < n4) {
        float4 v = ((const float4*)in)[i];
        split_store4(Hp, Lp, (size_t)i * 4, v);
    }
}

// ---------------- LayerNorm -> bf16 hi/lo ----------------
__global__ __launch_bounds__(256) void ln_kernel(const float* __restrict__ in,
                                                 const float* __restrict__ g,
                                                 const float* __restrict__ b,
                                                 __nv_bfloat16* __restrict__ outH,
                                                 __nv_bfloat16* __restrict__ outL) {
    int row = blockIdx.x;
    const float4* inr = (const float4*)(in + (size_t)row * D_);
    float4 v = inr[threadIdx.x];
    float s  = v.x + v.y + v.z + v.w;
    float ss = v.x*v.x + v.y*v.y + v.z*v.z + v.w*v.w;
    #pragma unroll
    for (int o = 16; o > 0; o >>= 1) {
        s  += __shfl_xor_sync(0xffffffffu, s,  o);
        ss += __shfl_xor_sync(0xffffffffu, ss, o);
    }
    __shared__ float red[16];
    __shared__ float mv[2];
    int w = threadIdx.x >> 5, ln = threadIdx.x & 31;
    if (ln == 0) { red[w] = s; red[w + 8] = ss; }
    __syncthreads();
    if (threadIdx.x == 0) {
        float a = 0.f, q = 0.f;
        #pragma unroll
        for (int i = 0; i < 8; i++) { a += red[i]; q += red[i + 8]; }
        float mu = a * (1.0f / D_);
        mv[0] = mu;
        mv[1] = rsqrtf(q * (1.0f / D_) - mu * mu + 1e-6f);
    }
    __syncthreads();
    float mu = mv[0], rs = mv[1];
    float4 gg = ((const float4*)g)[threadIdx.x];
    float4 bb = ((const float4*)b)[threadIdx.x];
    float4 o4;
    o4.x = (v.x - mu) * rs * gg.x + bb.x;
    o4.y = (v.y - mu) * rs * gg.y + bb.y;
    o4.z = (v.z - mu) * rs * gg.z + bb.z;
    o4.w = (v.w - mu) * rs * gg.w + bb.w;
    split_store4(outH, outL, (size_t)row * D_ + threadIdx.x * 4, o4);
}

// ---------------- HMMA bf16x3 NT GEMM ----------------
enum { EPI_QKV = 0, EPI_RES = 1, EPI_BIAS_RELU = 2, EPI_BIAS_RES = 3 };

static __device__ __forceinline__ void load_chunk(uint32_t stage,
    const __nv_bfloat16* __restrict__ Ah, const __nv_bfloat16* __restrict__ Al,
    const __nv_bfloat16* __restrict__ Bh, const __nv_bfloat16* __restrict__ Bl,
    int bm, int bn, int kc, int K, int tid)
{
    #pragma unroll
    for (int it = 0; it < 4; it++) {
        int e = tid + it * 256;        // 0..1023
        int row = e >> 3, seg = e & 7;
        uint32_t off = (uint32_t)(row * 128 + seg * 16);
        uint32_t sw  = off ^ ((off >> 3) & 0x70u);
        size_t ga = (size_t)(bm + row) * K + (size_t)kc * 64 + seg * 8;
        size_t gb = (size_t)(bn + row) * K + (size_t)kc * 64 + seg * 8;
        cp16(stage +     0u + sw, Ah + ga);
        cp16(stage + 16384u + sw, Al + ga);
        cp16(stage + 32768u + sw, Bh + gb);
        cp16(stage + 49152u + sw, Bl + gb);
    }
}

template <int EPI>
__global__ __launch_bounds__(256)
void mm_hmma(const __nv_bfloat16* __restrict__ Ah, const __nv_bfloat16* __restrict__ Al,
             const __nv_bfloat16* __restrict__ Bh, const __nv_bfloat16* __restrict__ Bl,
             float* __restrict__ outF,
             __nv_bfloat16* __restrict__ outH, __nv_bfloat16* __restrict__ outL,
             const float* __restrict__ bias, const float* __restrict__ res,
             int M, int N, int K)
{
    extern __shared__ char smem[];
    uint32_t tiles = s2u(smem);
    int tid = threadIdx.x, wid = tid >> 5, lane = tid & 31;
    int bm = blockIdx.y * 128, bn = blockIdx.x * 128;
    int wm = wid & 1, wn = wid >> 1;       // warp 64m x 32n tile
    int g = lane >> 3, lr = lane & 7;

    float acc[4][4][4];
    #pragma unroll
    for (int mt = 0; mt < 4; mt++)
        #pragma unroll
        for (int nt = 0; nt < 4; nt++)
            #pragma unroll
            for (int j = 0; j < 4; j++) acc[mt][nt][j] = 0.f;

    const int nc = K >> 6;
    load_chunk(tiles, Ah, Al, Bh, Bl, bm, bn, 0, K, tid);
    cp_commit();

    for (int i = 0; i < nc; i++) {
        if (i > 0) __syncthreads();
        if (i + 1 < nc) {
            load_chunk(tiles + (uint32_t)((i + 1) & 1) * 65536u, Ah, Al, Bh, Bl, bm, bn, i + 1, K, tid);
            cp_commit();
            cp_wait1();
        } else {
            cp_wait0();
        }
        __syncthreads();
        uint32_t st = tiles + (uint32_t)(i & 1) * 65536u;
        uint32_t stAh = st, stAl = st + 16384u, stBh = st + 32768u, stBl = st + 49152u;

        #pragma unroll
        for (int ks = 0; ks < 4; ks++) {
            uint32_t ah[4][4], al[4][4], bh[4][2], bl[4][2];
            int ka = ks * 32 + (g >> 1) * 16;
            int kb = ks * 32 + (g & 1) * 16;
            #pragma unroll
            for (int mt = 0; mt < 4; mt++) {
                int arow = wm * 64 + mt * 16 + (g & 1) * 8 + lr;
                uint32_t ao = (uint32_t)(arow * 128) + ((uint32_t)ka ^ (uint32_t)((arow & 7) << 4));
                ldsm_x4(ah[mt], stAh + ao);
                ldsm_x4(al[mt], stAl + ao);
            }
            #pragma unroll
            for (int nt = 0; nt < 4; nt++) {
                int brow = wn * 32 + nt * 8 + lr;
                uint32_t bo = (uint32_t)(brow * 128) + ((uint32_t)kb ^ (uint32_t)((brow & 7) << 4));
                ldsm_x2(bh[nt], stBh + bo);
                ldsm_x2(bl[nt], stBl + bo);
            }
            #pragma unroll
            for (int mt = 0; mt < 4; mt++)
                #pragma unroll
                for (int nt = 0; nt < 4; nt++) {
                    mma16816(acc[mt][nt], ah[mt], bh[nt]);
                    mma16816(acc[mt][nt], ah[mt], bl[nt]);
                    mma16816(acc[mt][nt], al[mt], bh[nt]);
                }
        }
    }

    int r = lane >> 2, c = lane & 3;
    #pragma unroll
    for (int mt = 0; mt < 4; mt++) {
        int m0 = bm + wm * 64 + mt * 16 + r;
        #pragma unroll
        for (int nt = 0; nt < 4; nt++) {
            int n = bn + wn * 32 + nt * 8 + c * 2;
            float d0 = acc[mt][nt][0], d1 = acc[mt][nt][1];
            float d2 = acc[mt][nt][2], d3 = acc[mt][nt][3];
            if (EPI == EPI_QKV) {
                int mat = n >> 10, nn = n & 1023;
                int bb = m0 >> 11, l = m0 & 2047, hh = nn >> 6, dd = nn & 63;
                size_t base = (size_t)mat * ((size_t)BH_ * L_ * DK_)
                            + (((size_t)(bb * H_ + hh) * L_ + l) * DK_ + dd);
                split_store2(outH, outL, base, d0, d1);
                split_store2(outH, outL, base + 8 * DK_, d2, d3);
            } else if (EPI == EPI_RES) {
                size_t off = (size_t)m0 * N + n;
                float2 r0 = *(const float2*)(res + off);
                float2 r1 = *(const float2*)(res + off + 8*(size_t)N);
                *(float2*)(outF + off)              = make_float2(d0 + r0.x, d1 + r0.y);
                *(float2*)(outF + off + 8*(size_t)N)= make_float2(d2 + r1.x, d3 + r1.y);
            } else if (EPI == EPI_BIAS_RELU) {
                size_t off = (size_t)m0 * N + n;
                float2 bv = *(const float2*)(bias + n);
                split_store2(outH, outL, off,
                             fmaxf(d0 + bv.x, 0.f), fmaxf(d1 + bv.y, 0.f));
                split_store2(outH, outL, off + 8*(size_t)N,
                             fmaxf(d2 + bv.x, 0.f), fmaxf(d3 + bv.y, 0.f));
            } else { // EPI_BIAS_RES
                size_t off = (size_t)m0 * N + n;
                float2 bv = *(const float2*)(bias + n);
                float2 r0 = *(const float2*)(res + off);
                float2 r1 = *(const float2*)(res + off + 8*(size_t)N);
                *(float2*)(outF + off)               = make_float2(d0 + bv.x + r0.x, d1 + bv.y + r0.y);
                *(float2*)(outF + off + 8*(size_t)N) = make_float2(d2 + bv.x + r1.x, d3 + bv.y + r1.y);
            }
        }
    }
}

// ---------------- HMMA fused attention ----------------
// CTA = (qtile 128, h, b), 8 warps x 16 rows. K-tiles of 64 keys, double buffered.
// smem: Qh 16K | Ql 16K | 2 stages x {Kh,Kl,Vh,Vl 8K each} | msk 8K | rs 512B
#define AS_QH   0u
#define AS_QL   16384u
#define AS_ST   32768u
#define AS_MSK  98304u
#define AS_RS   106496u
#define AS_TOT  (106496 + 512)

__global__ __launch_bounds__(256, 1)
void attn_mma(const __nv_bfloat16* __restrict__ Qh, const __nv_bfloat16* __restrict__ Ql,
              const __nv_bfloat16* __restrict__ Kh, const __nv_bfloat16* __restrict__ Kl,
              const __nv_bfloat16* __restrict__ Vh, const __nv_bfloat16* __restrict__ Vl,
              const float* __restrict__ prior, const int* __restrict__ mask,
              float* __restrict__ attn,
              __nv_bfloat16* __restrict__ Oh, __nv_bfloat16* __restrict__ Ol,
              float* __restrict__ rowsum)
{
    extern __shared__ char smc[];
    uint32_t sb = s2u(smc);
    float* msk = (float*)(smc + AS_MSK);
    float* rs  = (float*)(smc + AS_RS);

    int tid = threadIdx.x, warp = tid >> 5, lane = tid & 31;
    int qt = blockIdx.x, h = blockIdx.y, b = blockIdx.z;
    int bh = b * H_ + h;
    size_t qbase = ((size_t)bh * L_ + (size_t)qt * QT_) * DK_;

    // mask -> smem floats; rowsum init
    for (int i = tid; i < L_; i += 256) msk[i] = mask[b * L_ + i] ? 1.0f : 0.0f;
    if (tid < QT_) rs[tid] = 0.f;

    // Q tiles (group 0 with ktile 0)
    #pragma unroll
    for (int it = 0; it < 4; it++) {
        int e = tid + it * 256;
        int row = e >> 3, seg = e & 7;
        uint32_t off = (uint32_t)(row * 128 + seg * 16);
        uint32_t sw = off ^ ((off >> 3) & 0x70u);
        cp16(sb + AS_QH + sw, Qh + qbase + row * DK_ + seg * 8);
        cp16(sb + AS_QL + sw, Ql + qbase + row * DK_ + seg * 8);
    }
    // ktile 0
    {
        size_t kb0 = (size_t)bh * L_ * DK_;
        #pragma unroll
        for (int it = 0; it < 2; it++) {
            int e = tid + it * 256;
            int row = e >> 3, seg = e & 7;
            uint32_t off = (uint32_t)(row * 128 + seg * 16);
            uint32_t sw = off ^ ((off >> 3) & 0x70u);
            size_t gg = kb0 + row * DK_ + seg * 8;
            cp16(sb + AS_ST +      0u + sw, Kh + gg);
            cp16(sb + AS_ST +  8192u + sw, Kl + gg);
            cp16(sb + AS_ST + 16384u + sw, Vh + gg);
            cp16(sb + AS_ST + 24576u + sw, Vl + gg);
        }
    }
    cp_commit();

    float accO[8][4];
    #pragma unroll
    for (int nt = 0; nt < 8; nt++)
        #pragma unroll
        for (int j = 0; j < 4; j++) accO[nt][j] = 0.f;

    uint32_t qfh[4][4], qfl[4][4];

    int g = lane >> 3, lr = lane & 7;
    int r = lane >> 2, ci = lane & 3;
    int q0 = qt * QT_ + warp * 16 + r;
    const float* prow0 = prior + ((size_t)b * L_ + q0) * L_;
    const float* prow1 = prow0 + 8 * (size_t)L_;
    float* arow0 = attn + ((size_t)bh * L_ + q0) * L_;
    float* arow1 = arow0 + 8 * (size_t)L_;

    const int NKT = L_ / 64;  // 32
    for (int kt = 0; kt < NKT; kt++) {
        if (kt > 0) __syncthreads();
        if (kt + 1 < NKT) {
            size_t kbn = ((size_t)bh * L_ + (size_t)(kt + 1) * 64) * DK_;
            uint32_t stn = sb + AS_ST + (uint32_t)((kt + 1) & 1) * 32768u;
            #pragma unroll
            for (int it = 0; it < 2; it++) {
                int e = tid + it * 256;
                int row = e >> 3, seg = e & 7;
                uint32_t off = (uint32_t)(row * 128 + seg * 16);
                uint32_t sw = off ^ ((off >> 3) & 0x70u);
                size_t gg = kbn + row * DK_ + seg * 8;
                cp16(stn +      0u + sw, Kh + gg);
                cp16(stn +  8192u + sw, Kl + gg);
                cp16(stn + 16384u + sw, Vh + gg);
                cp16(stn + 24576u + sw, Vl + gg);
            }
            cp_commit();
            cp_wait1();
        } else {
            cp_wait0();
        }
        __syncthreads();

        if (kt == 0) {
            #pragma unroll
            for (int ks = 0; ks < 4; ks++) {
                int arow = warp * 16 + (g & 1) * 8 + lr;
                uint32_t ka = (uint32_t)(ks * 32 + (g >> 1) * 16);
                uint32_t ao = (uint32_t)(arow * 128) + (ka ^ (uint32_t)((arow & 7) << 4));
                ldsm_x4(qfh[ks], sb + AS_QH + ao);
                ldsm_x4(qfl[ks], sb + AS_QL + ao);
            }
        }

        uint32_t st = sb + AS_ST + (uint32_t)(kt & 1) * 32768u;

        // --- QK^T: accS[8 key-tiles][4] ---
        float accS[8][4];
        #pragma unroll
        for (int nt = 0; nt < 8; nt++)
            #pragma unroll
            for (int j = 0; j < 4; j++) accS[nt][j] = 0.f;

        #pragma unroll
        for (int ks = 0; ks < 4; ks++) {
            uint32_t kb = (uint32_t)(ks * 32 + (g & 1) * 16);
            #pragma unroll
            for (int nt = 0; nt < 8; nt++) {
                int brow = nt * 8 + lr;
                uint32_t bo = (uint32_t)(brow * 128) + (kb ^ (uint32_t)((brow & 7) << 4));
                uint32_t bh2[2], bl2[2];
                ldsm_x2(bh2, st + bo);
                ldsm_x2(bl2, st + 8192u + bo);
                mma16816(accS[nt], qfh[ks], bh2);
                mma16816(accS[nt], qfh[ks], bl2);
                mma16816(accS[nt], qfl[ks], bh2);
            }
        }

        // --- prior * mask * exp, attn store, rowsum, pack P frags ---
        int k0 = kt * 64;
        float sum0 = 0.f, sum1 = 0.f;
        uint32_t ph[4][4], pl[4][4];
        #pragma unroll
        for (int nt = 0; nt < 8; nt++) {
            int kk = k0 + nt * 8 + ci * 2;
            float2 pr0 = *(const float2*)(prow0 + kk);
            float2 pr1 = *(const float2*)(prow1 + kk);
            float mk0 = msk[kk], mk1 = msk[kk + 1];
            float e0 = mk0 * __expf(accS[nt][0] * 0.125f * pr0.x);
            float e1 = mk1 * __expf(accS[nt][1] * 0.125f * pr0.y);
            float e2 = mk0 * __expf(accS[nt][2] * 0.125f * pr1.x);
            float e3 = mk1 * __expf(accS[nt][3] * 0.125f * pr1.y);
            *(float2*)(arow0 + kk) = make_float2(e0, e1);
            *(float2*)(arow1 + kk) = make_float2(e2, e3);
            sum0 += e0 + e1;
            sum1 += e2 + e3;
            int t = nt >> 1, o = (nt & 1) * 2;
            float l0, l1, l2, l3;
            ph[t][o]     = pack_hi(e0, e1, &l0, &l1);
            ph[t][o + 1] = pack_hi(e2, e3, &l2, &l3);
            pl[t][o]     = pack_lo(l0, l1);
            pl[t][o + 1] = pack_lo(l2, l3);
        }
        sum0 += __shfl_xor_sync(0xffffffffu, sum0, 1);
        sum0 += __shfl_xor_sync(0xffffffffu, sum0, 2);
        sum1 += __shfl_xor_sync(0xffffffffu, sum1, 1);
        sum1 += __shfl_xor_sync(0xffffffffu, sum1, 2);
        if (ci == 0) {
            rs[warp * 16 + r]     += sum0;
            rs[warp * 16 + r + 8] += sum1;
        }

        // --- P @ V: accO += P[16x64] * V[64x64] (bf16x3) ---
        #pragma unroll
        for (int t = 0; t < 4; t++) {
            #pragma unroll
            for (int nt = 0; nt < 8; nt++) {
                int vrow = t * 16 + (lane & 15);
                uint32_t vo = (uint32_t)(vrow * 128) + ((uint32_t)(nt * 16) ^ (uint32_t)((vrow & 7) << 4));
                uint32_t vh2[2], vl2[2];
                ldsm_x2t(vh2, st + 16384u + vo);
                ldsm_x2t(vl2, st + 24576u + vo);
                mma16816(accO[nt], ph[t], vh2);
                mma16816(accO[nt], pl[t], vh2);
                mma16816(accO[nt], ph[t], vl2);
            }
        }
    }
    __syncthreads();

    int row0 = warp * 16 + r;
    float inv0 = 1.0f / rs[row0], inv1 = 1.0f / rs[row0 + 8];
    int l0 = qt * QT_ + row0;
    if (ci == 0) {
        rowsum[(size_t)bh * L_ + l0]     = rs[row0];
        rowsum[(size_t)bh * L_ + l0 + 8] = rs[row0 + 8];
    }
    #pragma unroll
    for (int nt = 0; nt < 8; nt++) {
        int dv = nt * 8 + ci * 2;
        size_t o0 = ((size_t)b * L_ + l0) * D_ + h * 64 + dv;
        size_t o1 = o0 + 8 * (size_t)D_;
        split_store2(Oh, Ol, o0, accO[nt][0] * inv0, accO[nt][1] * inv0);
        split_store2(Oh, Ol, o1, accO[nt][2] * inv1, accO[nt][3] * inv1);
    }
}

// ---------------- normalize attn rows ----------------
__global__ __launch_bounds__(256) void attn_norm(float* __restrict__ attn,
                                                 const float* __restrict__ rowsum) {
    int row = blockIdx.x;
    float inv = 1.0f / __ldg(rowsum + row);
    float4* p = (float4*)(attn + (size_t)row * L_);
    float4 a = p[threadIdx.x];
    a.x *= inv; a.y *= inv; a.z *= inv; a.w *= inv;
    p[threadIdx.x] = a;
    float4 c = p[threadIdx.x + 256];
    c.x *= inv; c.y *= inv; c.z *= inv; c.w *= inv;
    p[threadIdx.x + 256] = c;
}

// ---------------- host launcher ----------------
extern "C" void kernel_launch(void* const* d_in, const int* in_sizes, int n_in,
                              void* d_out, int out_size) {
    const float* src   = (const float*)d_in[0];
    const int*   mask  = (const int*)d_in[1];
    const float* prior = (const float*)d_in[2];
    const float* ln1_g = (const float*)d_in[3];
    const float* ln1_b = (const float*)d_in[4];
    const float* wq    = (const float*)d_in[5];
    const float* wk    = (const float*)d_in[6];
    const float* wv    = (const float*)d_in[7];
    const float* fc_w  = (const float*)d_in[8];
    const float* ln2_g = (const float*)d_in[9];
    const float* ln2_b = (const float*)d_in[10];
    const float* w1_w  = (const float*)d_in[11];
    const float* w1_b  = (const float*)d_in[12];
    const float* w2_w  = (const float*)d_in[13];
    const float* w2_b  = (const float*)d_in[14];

    float* out      = (float*)d_out;
    float* y_out    = out;                       // [B,L,D]
    float* attn_out = out + (size_t)M_ * D_;     // [B,H,L,L]

    __nv_bfloat16 *xh, *xl, *zh, *zl, *oh, *ol, *hh, *hl, *qkvh, *qkvl;
    __nv_bfloat16 *wqkvh, *wqkvl, *fch, *fcl, *w1h, *w1l, *w2h, *w2l;
    float *y, *rsum;
    cudaGetSymbolAddress((void**)&xh, g_xh);  cudaGetSymbolAddress((void**)&xl, g_xl);
    cudaGetSymbolAddress((void**)&zh, g_zh);  cudaGetSymbolAddress((void**)&zl, g_zl);
    cudaGetSymbolAddress((void**)&oh, g_oh);  cudaGetSymbolAddress((void**)&ol, g_ol);
    cudaGetSymbolAddress((void**)&hh, g_hh);  cudaGetSymbolAddress((void**)&hl, g_hl);
    cudaGetSymbolAddress((void**)&qkvh, g_qkvh); cudaGetSymbolAddress((void**)&qkvl, g_qkvl);
    cudaGetSymbolAddress((void**)&wqkvh, g_wqkvh); cudaGetSymbolAddress((void**)&wqkvl, g_wqkvl);
    cudaGetSymbolAddress((void**)&fch, g_fch); cudaGetSymbolAddress((void**)&fcl, g_fcl);
    cudaGetSymbolAddress((void**)&w1h, g_w1h); cudaGetSymbolAddress((void**)&w1l, g_w1l);
    cudaGetSymbolAddress((void**)&w2h, g_w2h); cudaGetSymbolAddress((void**)&w2l, g_w2l);
    cudaGetSymbolAddress((void**)&y, g_y);
    cudaGetSymbolAddress((void**)&rsum, g_rowsum);

    const int mm_smem = 2 * 65536;
    cudaFuncSetAttribute(mm_hmma<EPI_QKV>,       cudaFuncAttributeMaxDynamicSharedMemorySize, mm_smem);
    cudaFuncSetAttribute(mm_hmma<EPI_RES>,       cudaFuncAttributeMaxDynamicSharedMemorySize, mm_smem);
    cudaFuncSetAttribute(mm_hmma<EPI_BIAS_RELU>, cudaFuncAttributeMaxDynamicSharedMemorySize, mm_smem);
    cudaFuncSetAttribute(mm_hmma<EPI_BIAS_RES>,  cudaFuncAttributeMaxDynamicSharedMemorySize, mm_smem);
    cudaFuncSetAttribute(attn_mma,               cudaFuncAttributeMaxDynamicSharedMemorySize, AS_TOT);

    // 0) split weights to bf16 hi/lo (QKV concatenated)
    split_kernel<<<1024, 256>>>(wq,   wqkvh,                   wqkvl,                   (D_*D_) / 4);
    split_kernel<<<1024, 256>>>(wk,   wqkvh + (size_t)D_*D_,   wqkvl + (size_t)D_*D_,   (D_*D_) / 4);
    split_kernel<<<1024, 256>>>(wv,   wqkvh + 2*(size_t)D_*D_, wqkvl + 2*(size_t)D_*D_, (D_*D_) / 4);
    split_kernel<<<1024, 256>>>(fc_w, fch, fcl, (D_*H_*DK_) / 4);
    split_kernel<<<4096, 256>>>(w1_w, w1h, w1l, (DFF_*D_) / 4);
    split_kernel<<<4096, 256>>>(w2_w, w2h, w2l, (D_*DFF_) / 4);

    // 1) LN1 -> x split
    ln_kernel<<<M_, 256>>>(src, ln1_g, ln1_b, xh, xl);

    // 2) fused QKV projection (N=3072) -> bf16 hi/lo packed [3][b,h,l,dk]
    mm_hmma<EPI_QKV><<<dim3(QKVN / 128, M_ / 128), 256, mm_smem>>>(
        xh, xl, wqkvh, wqkvl, nullptr, qkvh, qkvl, nullptr, nullptr, M_, QKVN, D_);

    const size_t QS = (size_t)BH_ * L_ * DK_;
    // 3) HMMA fused attention
    dim3 gattn(L_ / QT_, H_, B_);
    attn_mma<<<gattn, 256, AS_TOT>>>(qkvh, qkvl, qkvh + QS, qkvl + QS, qkvh + 2*QS, qkvl + 2*QS,
                                     prior, mask, attn_out, oh, ol, rsum);

    // 4) normalize attn rows
    attn_norm<<<BH_ * L_, 256>>>(attn_out, rsum);

    // 5) fc + residual -> y (fp32)
    mm_hmma<EPI_RES><<<dim3(D_ / 128, M_ / 128), 256, mm_smem>>>(
        oh, ol, fch, fcl, y, nullptr, nullptr, nullptr, src, M_, D_, D_);

    // 6) LN2 -> z split
    ln_kernel<<<M_, 256>>>(y, ln2_g, ln2_b, zh, zl);

    // 7) FFN up + ReLU -> h split (bf16)
    mm_hmma<EPI_BIAS_RELU><<<dim3(DFF_ / 128, M_ / 128), 256, mm_smem>>>(
        zh, zl, w1h, w1l, nullptr, hh, hl, w1_b, nullptr, M_, DFF_, D_);

    // 8) FFN down + bias + residual -> final y
    mm_hmma<EPI_BIAS_RES><<<dim3(D_ / 128, M_ / 128), 256, mm_smem>>>(
        hh, hl, w2h, w2l, y_out, nullptr, nullptr, w2_b, y, M_, D_, DFF_);
}

// round 5
// speedup vs baseline: 2.9637x; 1.0639x over previous
#include <cuda_runtime.h>
#include <cuda_bf16.h>
#include <stdint.h>
#include <math.h>

#define B_   4
#define L_   2048
#define D_   1024
#define H_   16
#define DK_  64
#define DFF_ 4096
#define M_   (B_*L_)    // 8192 rows
#define BH_  (B_*H_)    // 64
#define QKVN (3*D_)     // 3072
#define QT_  128        // q rows per attention CTA

// ---------------- scratch (static device globals; no allocation) ----------------
__device__ __nv_bfloat16 g_xh[M_*D_],  g_xl[M_*D_];    // LN1 out split
__device__ __nv_bfloat16 g_zh[M_*D_],  g_zl[M_*D_];    // LN2 out split
__device__ __nv_bfloat16 g_oh[M_*D_],  g_ol[M_*D_];    // attn O split
__device__ __nv_bfloat16 g_hh[M_*DFF_],g_hl[M_*DFF_];  // FFN hidden split
__device__ __nv_bfloat16 g_qkvh[3*(size_t)M_*D_], g_qkvl[3*(size_t)M_*D_]; // packed [3][b,h,l,dk]
__device__ float g_y[M_*D_];
__device__ float g_rowsum[BH_*L_];
// weight splits (qkv combined rows 0..1023=Q, 1024..2047=K, 2048..3071=V)
__device__ __nv_bfloat16 g_wqkvh[QKVN*D_], g_wqkvl[QKVN*D_];
__device__ __nv_bfloat16 g_fch[D_*H_*DK_], g_fcl[D_*H_*DK_];
__device__ __nv_bfloat16 g_w1h[DFF_*D_],   g_w1l[DFF_*D_];
__device__ __nv_bfloat16 g_w2h[D_*DFF_],   g_w2l[D_*DFF_];

// ---------------- small PTX helpers ----------------
static __device__ __forceinline__ uint32_t s2u(const void* p) {
    uint32_t a;
    asm("{ .reg .u64 t; cvta.to.shared.u64 t, %1; cvt.u32.u64 %0, t; }" : "=r"(a) : "l"(p));
    return a;
}
static __device__ __forceinline__ void cp16(uint32_t dst, const void* src) {
    asm volatile("cp.async.cg.shared.global [%0], [%1], 16;" :: "r"(dst), "l"(src) : "memory");
}
static __device__ __forceinline__ void cp_commit() { asm volatile("cp.async.commit_group;" ::: "memory"); }
static __device__ __forceinline__ void cp_wait1()  { asm volatile("cp.async.wait_group 1;" ::: "memory"); }
static __device__ __forceinline__ void cp_wait0()  { asm volatile("cp.async.wait_group 0;" ::: "memory"); }

static __device__ __forceinline__ void ldsm_x4(uint32_t* r, uint32_t addr) {
    asm volatile("ldmatrix.sync.aligned.m8n8.x4.shared.b16 {%0,%1,%2,%3}, [%4];"
                 : "=r"(r[0]), "=r"(r[1]), "=r"(r[2]), "=r"(r[3]) : "r"(addr));
}
static __device__ __forceinline__ void ldsm_x2(uint32_t* r, uint32_t addr) {
    asm volatile("ldmatrix.sync.aligned.m8n8.x2.shared.b16 {%0,%1}, [%2];"
                 : "=r"(r[0]), "=r"(r[1]) : "r"(addr));
}
static __device__ __forceinline__ void ldsm_x2t(uint32_t* r, uint32_t addr) {
    asm volatile("ldmatrix.sync.aligned.m8n8.x2.trans.shared.b16 {%0,%1}, [%2];"
                 : "=r"(r[0]), "=r"(r[1]) : "r"(addr));
}
static __device__ __forceinline__ void mma16816(float* d, const uint32_t* a, const uint32_t* b) {
    asm volatile("mma.sync.aligned.m16n8k16.row.col.f32.bf16.bf16.f32 "
                 "{%0,%1,%2,%3}, {%4,%5,%6,%7}, {%8,%9}, {%0,%1,%2,%3};"
                 : "+f"(d[0]), "+f"(d[1]), "+f"(d[2]), "+f"(d[3])
                 : "r"(a[0]), "r"(a[1]), "r"(a[2]), "r"(a[3]), "r"(b[0]), "r"(b[1]));
}

static __device__ __forceinline__ uint32_t pack_hi(float a, float b, float* la, float* lb) {
    __nv_bfloat16 h0 = __float2bfloat16(a), h1 = __float2bfloat16(b);
    *la = a - __bfloat162float(h0);
    *lb = b - __bfloat162float(h1);
    __nv_bfloat162 hp = __halves2bfloat162(h0, h1);
    return *(uint32_t*)&hp;
}
static __device__ __forceinline__ uint32_t pack_lo(float a, float b) {
    __nv_bfloat162 lp = __floats2bfloat162_rn(a, b);
    return *(uint32_t*)&lp;
}

// split floats -> hi/lo bf16 stores
static __device__ __forceinline__ void split_store4(__nv_bfloat16* __restrict__ Hp,
                                                    __nv_bfloat16* __restrict__ Lp,
                                                    size_t idx, float4 v) {
    __nv_bfloat16 h0 = __float2bfloat16(v.x), h1 = __float2bfloat16(v.y);
    __nv_bfloat16 h2 = __float2bfloat16(v.z), h3 = __float2bfloat16(v.w);
    float l0 = v.x - __bfloat162float(h0), l1 = v.y - __bfloat162float(h1);
    float l2 = v.z - __bfloat162float(h2), l3 = v.w - __bfloat162float(h3);
    __nv_bfloat162 hp0 = __halves2bfloat162(h0, h1), hp1 = __halves2bfloat162(h2, h3);
    __nv_bfloat162 lp0 = __floats2bfloat162_rn(l0, l1), lp1 = __floats2bfloat162_rn(l2, l3);
    uint2 hu = make_uint2(*(uint32_t*)&hp0, *(uint32_t*)&hp1);
    uint2 lu = make_uint2(*(uint32_t*)&lp0, *(uint32_t*)&lp1);
    *(uint2*)(Hp + idx) = hu;
    *(uint2*)(Lp + idx) = lu;
}
static __device__ __forceinline__ void split_store2(__nv_bfloat16* __restrict__ Hp,
                                                    __nv_bfloat16* __restrict__ Lp,
                                                    size_t idx, float a, float b) {
    __nv_bfloat16 h0 = __float2bfloat16(a), h1 = __float2bfloat16(b);
    float l0 = a - __bfloat162float(h0), l1 = b - __bfloat162float(h1);
    __nv_bfloat162 hp = __halves2bfloat162(h0, h1);
    __nv_bfloat162 lp = __floats2bfloat162_rn(l0, l1);
    *(uint32_t*)(Hp + idx) = *(uint32_t*)&hp;
    *(uint32_t*)(Lp + idx) = *(uint32_t*)&lp;
}

// ---------------- weight split: fp32 -> bf16 hi/lo ----------------
__global__ __launch_bounds__(256) void split_kernel(const float* __restrict__ in,
                                                    __nv_bfloat16* __restrict__ Hp,
                                                    __nv_bfloat16* __restrict__ Lp,
                                                    int n4) {
    int i = blockIdx.x * 256 + threadIdx.x;
    if (i < n4) {
        float4 v = ((const float4*)in)[i];
        split_store4(Hp, Lp, (size_t)i * 4, v);
    }
}

// ---------------- LayerNorm -> bf16 hi/lo ----------------
__global__ __launch_bounds__(256) void ln_kernel(const float* __restrict__ in,
                                                 const float* __restrict__ g,
                                                 const float* __restrict__ b,
                                                 __nv_bfloat16* __restrict__ outH,
                                                 __nv_bfloat16* __restrict__ outL) {
    int row = blockIdx.x;
    const float4* inr = (const float4*)(in + (size_t)row * D_);
    float4 v = inr[threadIdx.x];
    float s  = v.x + v.y + v.z + v.w;
    float ss = v.x*v.x + v.y*v.y + v.z*v.z + v.w*v.w;
    #pragma unroll
    for (int o = 16; o > 0; o >>= 1) {
        s  += __shfl_xor_sync(0xffffffffu, s,  o);
        ss += __shfl_xor_sync(0xffffffffu, ss, o);
    }
    __shared__ float red[16];
    __shared__ float mv[2];
    int w = threadIdx.x >> 5, ln = threadIdx.x & 31;
    if (ln == 0) { red[w] = s; red[w + 8] = ss; }
    __syncthreads();
    if (threadIdx.x == 0) {
        float a = 0.f, q = 0.f;
        #pragma unroll
        for (int i = 0; i < 8; i++) { a += red[i]; q += red[i + 8]; }
        float mu = a * (1.0f / D_);
        mv[0] = mu;
        mv[1] = rsqrtf(q * (1.0f / D_) - mu * mu + 1e-6f);
    }
    __syncthreads();
    float mu = mv[0], rs = mv[1];
    float4 gg = ((const float4*)g)[threadIdx.x];
    float4 bb = ((const float4*)b)[threadIdx.x];
    float4 o4;
    o4.x = (v.x - mu) * rs * gg.x + bb.x;
    o4.y = (v.y - mu) * rs * gg.y + bb.y;
    o4.z = (v.z - mu) * rs * gg.z + bb.z;
    o4.w = (v.w - mu) * rs * gg.w + bb.w;
    split_store4(outH, outL, (size_t)row * D_ + threadIdx.x * 4, o4);
}

// ---------------- HMMA bf16x3 NT GEMM (3-stage pipeline) ----------------
enum { EPI_QKV = 0, EPI_RES = 1, EPI_BIAS_RELU = 2, EPI_BIAS_RES = 3 };

static __device__ __forceinline__ void load_chunk(uint32_t stage,
    const __nv_bfloat16* __restrict__ Ah, const __nv_bfloat16* __restrict__ Al,
    const __nv_bfloat16* __restrict__ Bh, const __nv_bfloat16* __restrict__ Bl,
    int bm, int bn, int kc, int K, int tid)
{
    #pragma unroll
    for (int it = 0; it < 4; it++) {
        int e = tid + it * 256;        // 0..1023
        int row = e >> 3, seg = e & 7;
        uint32_t off = (uint32_t)(row * 128 + seg * 16);
        uint32_t sw  = off ^ ((off >> 3) & 0x70u);
        size_t ga = (size_t)(bm + row) * K + (size_t)kc * 64 + seg * 8;
        size_t gb = (size_t)(bn + row) * K + (size_t)kc * 64 + seg * 8;
        cp16(stage +     0u + sw, Ah + ga);
        cp16(stage + 16384u + sw, Al + ga);
        cp16(stage + 32768u + sw, Bh + gb);
        cp16(stage + 49152u + sw, Bl + gb);
    }
}

// DO_NORM: per chunk, also normalize a slice of the attention matrix (hides
// attn_norm's DRAM traffic under the tensor-pipe time). Requires nc == 16.
template <int EPI, int DO_NORM>
__global__ __launch_bounds__(256, 1)
void mm_hmma(const __nv_bfloat16* __restrict__ Ah, const __nv_bfloat16* __restrict__ Al,
             const __nv_bfloat16* __restrict__ Bh, const __nv_bfloat16* __restrict__ Bl,
             float* __restrict__ outF,
             __nv_bfloat16* __restrict__ outH, __nv_bfloat16* __restrict__ outL,
             const float* __restrict__ bias, const float* __restrict__ res,
             int M, int N, int K,
             float* __restrict__ normA, const float* __restrict__ normR)
{
    extern __shared__ char smem[];
    uint32_t tiles = s2u(smem);
    int tid = threadIdx.x, wid = tid >> 5, lane = tid & 31;
    int bm = blockIdx.y * 128, bn = blockIdx.x * 128;
    int wm = wid & 1, wn = wid >> 1;       // warp 64m x 32n tile
    int g = lane >> 3, lr = lane & 7;

    float acc[4][4][4];
    #pragma unroll
    for (int mt = 0; mt < 4; mt++)
        #pragma unroll
        for (int nt = 0; nt < 4; nt++)
            #pragma unroll
            for (int j = 0; j < 4; j++) acc[mt][nt][j] = 0.f;

    const int nc = K >> 6;
    load_chunk(tiles,          Ah, Al, Bh, Bl, bm, bn, 0, K, tid);
    cp_commit();
    load_chunk(tiles + 65536u, Ah, Al, Bh, Bl, bm, bn, 1, K, tid);
    cp_commit();

    size_t ctaLin = (size_t)blockIdx.y * gridDim.x + blockIdx.x;

    for (int i = 0; i < nc; i++) {
        if (i == nc - 1) cp_wait0(); else cp_wait1();
        __syncthreads();
        if (i + 2 < nc) {
            load_chunk(tiles + (uint32_t)((i + 2) % 3) * 65536u, Ah, Al, Bh, Bl, bm, bn, i + 2, K, tid);
            cp_commit();
        }

        float4 nv[8]; float ni[8];
        if (DO_NORM) {
            size_t f4b = ctaLin * 32768u + (size_t)i * 2048u + (size_t)tid;
            #pragma unroll
            for (int j = 0; j < 8; j++) {
                size_t f = f4b + (size_t)(j * 256);
                nv[j] = ((const float4*)normA)[f];
                ni[j] = normR[f >> 9];
            }
        }

        uint32_t st = tiles + (uint32_t)(i % 3) * 65536u;
        uint32_t stAh = st, stAl = st + 16384u, stBh = st + 32768u, stBl = st + 49152u;

        #pragma unroll
        for (int ks = 0; ks < 4; ks++) {
            uint32_t ah[4][4], al[4][4], bh[4][2], bl[4][2];
            int ka = ks * 32 + (g >> 1) * 16;
            int kb = ks * 32 + (g & 1) * 16;
            #pragma unroll
            for (int mt = 0; mt < 4; mt++) {
                int arow = wm * 64 + mt * 16 + (g & 1) * 8 + lr;
                uint32_t ao = (uint32_t)(arow * 128) + ((uint32_t)ka ^ (uint32_t)((arow & 7) << 4));
                ldsm_x4(ah[mt], stAh + ao);
                ldsm_x4(al[mt], stAl + ao);
            }
            #pragma unroll
            for (int nt = 0; nt < 4; nt++) {
                int brow = wn * 32 + nt * 8 + lr;
                uint32_t bo = (uint32_t)(brow * 128) + ((uint32_t)kb ^ (uint32_t)((brow & 7) << 4));
                ldsm_x2(bh[nt], stBh + bo);
                ldsm_x2(bl[nt], stBl + bo);
            }
            #pragma unroll
            for (int mt = 0; mt < 4; mt++)
                #pragma unroll
                for (int nt = 0; nt < 4; nt++) {
                    mma16816(acc[mt][nt], ah[mt], bh[nt]);
                    mma16816(acc[mt][nt], ah[mt], bl[nt]);
                    mma16816(acc[mt][nt], al[mt], bh[nt]);
                }
        }

        if (DO_NORM) {
            size_t f4b = ctaLin * 32768u + (size_t)i * 2048u + (size_t)tid;
            #pragma unroll
            for (int j = 0; j < 8; j++) {
                size_t f = f4b + (size_t)(j * 256);
                float inv = 1.0f / ni[j];
                float4 v = nv[j];
                v.x *= inv; v.y *= inv; v.z *= inv; v.w *= inv;
                ((float4*)normA)[f] = v;
            }
        }
    }

    int r = lane >> 2, c = lane & 3;
    #pragma unroll
    for (int mt = 0; mt < 4; mt++) {
        int m0 = bm + wm * 64 + mt * 16 + r;
        #pragma unroll
        for (int nt = 0; nt < 4; nt++) {
            int n = bn + wn * 32 + nt * 8 + c * 2;
            float d0 = acc[mt][nt][0], d1 = acc[mt][nt][1];
            float d2 = acc[mt][nt][2], d3 = acc[mt][nt][3];
            if (EPI == EPI_QKV) {
                int mat = n >> 10, nn = n & 1023;
                int bb = m0 >> 11, l = m0 & 2047, hh = nn >> 6, dd = nn & 63;
                size_t base = (size_t)mat * ((size_t)BH_ * L_ * DK_)
                            + (((size_t)(bb * H_ + hh) * L_ + l) * DK_ + dd);
                split_store2(outH, outL, base, d0, d1);
                split_store2(outH, outL, base + 8 * DK_, d2, d3);
            } else if (EPI == EPI_RES) {
                size_t off = (size_t)m0 * N + n;
                float2 r0 = *(const float2*)(res + off);
                float2 r1 = *(const float2*)(res + off + 8*(size_t)N);
                *(float2*)(outF + off)              = make_float2(d0 + r0.x, d1 + r0.y);
                *(float2*)(outF + off + 8*(size_t)N)= make_float2(d2 + r1.x, d3 + r1.y);
            } else if (EPI == EPI_BIAS_RELU) {
                size_t off = (size_t)m0 * N + n;
                float2 bv = *(const float2*)(bias + n);
                split_store2(outH, outL, off,
                             fmaxf(d0 + bv.x, 0.f), fmaxf(d1 + bv.y, 0.f));
                split_store2(outH, outL, off + 8*(size_t)N,
                             fmaxf(d2 + bv.x, 0.f), fmaxf(d3 + bv.y, 0.f));
            } else { // EPI_BIAS_RES
                size_t off = (size_t)m0 * N + n;
                float2 bv = *(const float2*)(bias + n);
                float2 r0 = *(const float2*)(res + off);
                float2 r1 = *(const float2*)(res + off + 8*(size_t)N);
                *(float2*)(outF + off)               = make_float2(d0 + bv.x + r0.x, d1 + bv.y + r0.y);
                *(float2*)(outF + off + 8*(size_t)N) = make_float2(d2 + bv.x + r1.x, d3 + bv.y + r1.y);
            }
        }
    }
}

// ---------------- HMMA fused attention (3-stage pipeline) ----------------
// CTA = (qtile 128, h, b), 8 warps x 16 rows. K-tiles of 64 keys, triple buffered.
// smem: Qh 16K | Ql 16K | 3 stages x {Kh,Kl,Vh,Vl 8K each} | msk 8K | rs 512B
#define AS_QH   0u
#define AS_QL   16384u
#define AS_ST   32768u
#define AS_MSK  131072u
#define AS_RS   139264u
#define AS_TOT  (139264 + 512)

static __device__ __forceinline__ void attn_load_tile(uint32_t stn,
    const __nv_bfloat16* __restrict__ Kh, const __nv_bfloat16* __restrict__ Kl,
    const __nv_bfloat16* __restrict__ Vh, const __nv_bfloat16* __restrict__ Vl,
    size_t kbn, int tid)
{
    #pragma unroll
    for (int it = 0; it < 2; it++) {
        int e = tid + it * 256;
        int row = e >> 3, seg = e & 7;
        uint32_t off = (uint32_t)(row * 128 + seg * 16);
        uint32_t sw = off ^ ((off >> 3) & 0x70u);
        size_t gg = kbn + row * DK_ + seg * 8;
        cp16(stn +      0u + sw, Kh + gg);
        cp16(stn +  8192u + sw, Kl + gg);
        cp16(stn + 16384u + sw, Vh + gg);
        cp16(stn + 24576u + sw, Vl + gg);
    }
}

__global__ __launch_bounds__(256, 1)
void attn_mma(const __nv_bfloat16* __restrict__ Qh, const __nv_bfloat16* __restrict__ Ql,
              const __nv_bfloat16* __restrict__ Kh, const __nv_bfloat16* __restrict__ Kl,
              const __nv_bfloat16* __restrict__ Vh, const __nv_bfloat16* __restrict__ Vl,
              const float* __restrict__ prior, const int* __restrict__ mask,
              float* __restrict__ attn,
              __nv_bfloat16* __restrict__ Oh, __nv_bfloat16* __restrict__ Ol,
              float* __restrict__ rowsum)
{
    extern __shared__ char smc[];
    uint32_t sb = s2u(smc);
    float* msk = (float*)(smc + AS_MSK);
    float* rs  = (float*)(smc + AS_RS);

    int tid = threadIdx.x, warp = tid >> 5, lane = tid & 31;
    int qt = blockIdx.x, h = blockIdx.y, b = blockIdx.z;
    int bh = b * H_ + h;
    size_t qbase = ((size_t)bh * L_ + (size_t)qt * QT_) * DK_;
    size_t kvbase = (size_t)bh * L_ * DK_;

    // mask -> smem floats; rowsum init
    for (int i = tid; i < L_; i += 256) msk[i] = mask[b * L_ + i] ? 1.0f : 0.0f;
    if (tid < QT_) rs[tid] = 0.f;

    // Q tiles + ktile 0 (group 0)
    #pragma unroll
    for (int it = 0; it < 4; it++) {
        int e = tid + it * 256;
        int row = e >> 3, seg = e & 7;
        uint32_t off = (uint32_t)(row * 128 + seg * 16);
        uint32_t sw = off ^ ((off >> 3) & 0x70u);
        cp16(sb + AS_QH + sw, Qh + qbase + row * DK_ + seg * 8);
        cp16(sb + AS_QL + sw, Ql + qbase + row * DK_ + seg * 8);
    }
    attn_load_tile(sb + AS_ST, Kh, Kl, Vh, Vl, kvbase, tid);
    cp_commit();
    // ktile 1 (group 1)
    attn_load_tile(sb + AS_ST + 32768u, Kh, Kl, Vh, Vl, kvbase + 64 * DK_, tid);
    cp_commit();

    float accO[8][4];
    #pragma unroll
    for (int nt = 0; nt < 8; nt++)
        #pragma unroll
        for (int j = 0; j < 4; j++) accO[nt][j] = 0.f;

    uint32_t qfh[4][4], qfl[4][4];

    int g = lane >> 3, lr = lane & 7;
    int r = lane >> 2, ci = lane & 3;
    int q0 = qt * QT_ + warp * 16 + r;
    const float* prow0 = prior + ((size_t)b * L_ + q0) * L_;
    const float* prow1 = prow0 + 8 * (size_t)L_;
    float* arow0 = attn + ((size_t)bh * L_ + q0) * L_;
    float* arow1 = arow0 + 8 * (size_t)L_;

    const int NKT = L_ / 64;  // 32
    for (int kt = 0; kt < NKT; kt++) {
        if (kt == NKT - 1) cp_wait0(); else cp_wait1();
        __syncthreads();
        if (kt + 2 < NKT) {
            attn_load_tile(sb + AS_ST + (uint32_t)((kt + 2) % 3) * 32768u,
                           Kh, Kl, Vh, Vl, kvbase + (size_t)(kt + 2) * 64 * DK_, tid);
            cp_commit();
        }

        if (kt == 0) {
            #pragma unroll
            for (int ks = 0; ks < 4; ks++) {
                int arow = warp * 16 + (g & 1) * 8 + lr;
                uint32_t ka = (uint32_t)(ks * 32 + (g >> 1) * 16);
                uint32_t ao = (uint32_t)(arow * 128) + (ka ^ (uint32_t)((arow & 7) << 4));
                ldsm_x4(qfh[ks], sb + AS_QH + ao);
                ldsm_x4(qfl[ks], sb + AS_QL + ao);
            }
        }

        uint32_t st = sb + AS_ST + (uint32_t)(kt % 3) * 32768u;

        // --- QK^T: accS[8 key-tiles][4] ---
        float accS[8][4];
        #pragma unroll
        for (int nt = 0; nt < 8; nt++)
            #pragma unroll
            for (int j = 0; j < 4; j++) accS[nt][j] = 0.f;

        #pragma unroll
        for (int ks = 0; ks < 4; ks++) {
            uint32_t kb = (uint32_t)(ks * 32 + (g & 1) * 16);
            #pragma unroll
            for (int nt = 0; nt < 8; nt++) {
                int brow = nt * 8 + lr;
                uint32_t bo = (uint32_t)(brow * 128) + (kb ^ (uint32_t)((brow & 7) << 4));
                uint32_t bh2[2], bl2[2];
                ldsm_x2(bh2, st + bo);
                ldsm_x2(bl2, st + 8192u + bo);
                mma16816(accS[nt], qfh[ks], bh2);
                mma16816(accS[nt], qfh[ks], bl2);
                mma16816(accS[nt], qfl[ks], bh2);
            }
        }

        // --- prior * mask * exp, attn store, rowsum, pack P frags ---
        int k0 = kt * 64;
        float sum0 = 0.f, sum1 = 0.f;
        uint32_t ph[4][4], pl[4][4];
        #pragma unroll
        for (int nt = 0; nt < 8; nt++) {
            int kk = k0 + nt * 8 + ci * 2;
            float2 pr0 = *(const float2*)(prow0 + kk);
            float2 pr1 = *(const float2*)(prow1 + kk);
            float mk0 = msk[kk], mk1 = msk[kk + 1];
            float e0 = mk0 * __expf(accS[nt][0] * 0.125f * pr0.x);
            float e1 = mk1 * __expf(accS[nt][1] * 0.125f * pr0.y);
            float e2 = mk0 * __expf(accS[nt][2] * 0.125f * pr1.x);
            float e3 = mk1 * __expf(accS[nt][3] * 0.125f * pr1.y);
            *(float2*)(arow0 + kk) = make_float2(e0, e1);
            *(float2*)(arow1 + kk) = make_float2(e2, e3);
            sum0 += e0 + e1;
            sum1 += e2 + e3;
            int t = nt >> 1, o = (nt & 1) * 2;
            float l0, l1, l2, l3;
            ph[t][o]     = pack_hi(e0, e1, &l0, &l1);
            ph[t][o + 1] = pack_hi(e2, e3, &l2, &l3);
            pl[t][o]     = pack_lo(l0, l1);
            pl[t][o + 1] = pack_lo(l2, l3);
        }
        sum0 += __shfl_xor_sync(0xffffffffu, sum0, 1);
        sum0 += __shfl_xor_sync(0xffffffffu, sum0, 2);
        sum1 += __shfl_xor_sync(0xffffffffu, sum1, 1);
        sum1 += __shfl_xor_sync(0xffffffffu, sum1, 2);
        if (ci == 0) {
            rs[warp * 16 + r]     += sum0;
            rs[warp * 16 + r + 8] += sum1;
        }

        // --- P @ V: accO += P[16x64] * V[64x64] (bf16x3) ---
        #pragma unroll
        for (int t = 0; t < 4; t++) {
            #pragma unroll
            for (int nt = 0; nt < 8; nt++) {
                int vrow = t * 16 + (lane & 15);
                uint32_t vo = (uint32_t)(vrow * 128) + ((uint32_t)(nt * 16) ^ (uint32_t)((vrow & 7) << 4));
                uint32_t vh2[2], vl2[2];
                ldsm_x2t(vh2, st + 16384u + vo);
                ldsm_x2t(vl2, st + 24576u + vo);
                mma16816(accO[nt], ph[t], vh2);
                mma16816(accO[nt], pl[t], vh2);
                mma16816(accO[nt], ph[t], vl2);
            }
        }
    }
    __syncthreads();

    int row0 = warp * 16 + r;
    float inv0 = 1.0f / rs[row0], inv1 = 1.0f / rs[row0 + 8];
    int l0 = qt * QT_ + row0;
    if (ci == 0) {
        rowsum[(size_t)bh * L_ + l0]     = rs[row0];
        rowsum[(size_t)bh * L_ + l0 + 8] = rs[row0 + 8];
    }
    #pragma unroll
    for (int nt = 0; nt < 8; nt++) {
        int dv = nt * 8 + ci * 2;
        size_t o0 = ((size_t)b * L_ + l0) * D_ + h * 64 + dv;
        size_t o1 = o0 + 8 * (size_t)D_;
        split_store2(Oh, Ol, o0, accO[nt][0] * inv0, accO[nt][1] * inv0);
        split_store2(Oh, Ol, o1, accO[nt][2] * inv1, accO[nt][3] * inv1);
    }
}

// ---------------- host launcher ----------------
extern "C" void kernel_launch(void* const* d_in, const int* in_sizes, int n_in,
                              void* d_out, int out_size) {
    const float* src   = (const float*)d_in[0];
    const int*   mask  = (const int*)d_in[1];
    const float* prior = (const float*)d_in[2];
    const float* ln1_g = (const float*)d_in[3];
    const float* ln1_b = (const float*)d_in[4];
    const float* wq    = (const float*)d_in[5];
    const float* wk    = (const float*)d_in[6];
    const float* wv    = (const float*)d_in[7];
    const float* fc_w  = (const float*)d_in[8];
    const float* ln2_g = (const float*)d_in[9];
    const float* ln2_b = (const float*)d_in[10];
    const float* w1_w  = (const float*)d_in[11];
    const float* w1_b  = (const float*)d_in[12];
    const float* w2_w  = (const float*)d_in[13];
    const float* w2_b  = (const float*)d_in[14];

    float* out      = (float*)d_out;
    float* y_out    = out;                       // [B,L,D]
    float* attn_out = out + (size_t)M_ * D_;     // [B,H,L,L]

    __nv_bfloat16 *xh, *xl, *zh, *zl, *oh, *ol, *hh, *hl, *qkvh, *qkvl;
    __nv_bfloat16 *wqkvh, *wqkvl, *fch, *fcl, *w1h, *w1l, *w2h, *w2l;
    float *y, *rsum;
    cudaGetSymbolAddress((void**)&xh, g_xh);  cudaGetSymbolAddress((void**)&xl, g_xl);
    cudaGetSymbolAddress((void**)&zh, g_zh);  cudaGetSymbolAddress((void**)&zl, g_zl);
    cudaGetSymbolAddress((void**)&oh, g_oh);  cudaGetSymbolAddress((void**)&ol, g_ol);
    cudaGetSymbolAddress((void**)&hh, g_hh);  cudaGetSymbolAddress((void**)&hl, g_hl);
    cudaGetSymbolAddress((void**)&qkvh, g_qkvh); cudaGetSymbolAddress((void**)&qkvl, g_qkvl);
    cudaGetSymbolAddress((void**)&wqkvh, g_wqkvh); cudaGetSymbolAddress((void**)&wqkvl, g_wqkvl);
    cudaGetSymbolAddress((void**)&fch, g_fch); cudaGetSymbolAddress((void**)&fcl, g_fcl);
    cudaGetSymbolAddress((void**)&w1h, g_w1h); cudaGetSymbolAddress((void**)&w1l, g_w1l);
    cudaGetSymbolAddress((void**)&w2h, g_w2h); cudaGetSymbolAddress((void**)&w2l, g_w2l);
    cudaGetSymbolAddress((void**)&y, g_y);
    cudaGetSymbolAddress((void**)&rsum, g_rowsum);

    const int mm_smem = 3 * 65536;   // 192 KB (3 stages)
    cudaFuncSetAttribute(mm_hmma<EPI_QKV, 0>,       cudaFuncAttributeMaxDynamicSharedMemorySize, mm_smem);
    cudaFuncSetAttribute(mm_hmma<EPI_RES, 0>,       cudaFuncAttributeMaxDynamicSharedMemorySize, mm_smem);
    cudaFuncSetAttribute(mm_hmma<EPI_BIAS_RELU, 1>, cudaFuncAttributeMaxDynamicSharedMemorySize, mm_smem);
    cudaFuncSetAttribute(mm_hmma<EPI_BIAS_RES, 0>,  cudaFuncAttributeMaxDynamicSharedMemorySize, mm_smem);
    cudaFuncSetAttribute(attn_mma,                  cudaFuncAttributeMaxDynamicSharedMemorySize, AS_TOT);

    // 0) split weights to bf16 hi/lo (QKV concatenated)
    split_kernel<<<1024, 256>>>(wq,   wqkvh,                   wqkvl,                   (D_*D_) / 4);
    split_kernel<<<1024, 256>>>(wk,   wqkvh + (size_t)D_*D_,   wqkvl + (size_t)D_*D_,   (D_*D_) / 4);
    split_kernel<<<1024, 256>>>(wv,   wqkvh + 2*(size_t)D_*D_, wqkvl + 2*(size_t)D_*D_, (D_*D_) / 4);
    split_kernel<<<1024, 256>>>(fc_w, fch, fcl, (D_*H_*DK_) / 4);
    split_kernel<<<4096, 256>>>(w1_w, w1h, w1l, (DFF_*D_) / 4);
    split_kernel<<<4096, 256>>>(w2_w, w2h, w2l, (D_*DFF_) / 4);

    // 1) LN1 -> x split
    ln_kernel<<<M_, 256>>>(src, ln1_g, ln1_b, xh, xl);

    // 2) fused QKV projection (N=3072) -> bf16 hi/lo packed [3][b,h,l,dk]
    mm_hmma<EPI_QKV, 0><<<dim3(QKVN / 128, M_ / 128), 256, mm_smem>>>(
        xh, xl, wqkvh, wqkvl, nullptr, qkvh, qkvl, nullptr, nullptr, M_, QKVN, D_, nullptr, nullptr);

    const size_t QS = (size_t)BH_ * L_ * DK_;
    // 3) HMMA fused attention (writes unnormalized attn + rowsum + normalized O)
    dim3 gattn(L_ / QT_, H_, B_);
    attn_mma<<<gattn, 256, AS_TOT>>>(qkvh, qkvl, qkvh + QS, qkvl + QS, qkvh + 2*QS, qkvl + 2*QS,
                                     prior, mask, attn_out, oh, ol, rsum);

    // 4) fc + residual -> y (fp32)
    mm_hmma<EPI_RES, 0><<<dim3(D_ / 128, M_ / 128), 256, mm_smem>>>(
        oh, ol, fch, fcl, y, nullptr, nullptr, nullptr, src, M_, D_, D_, nullptr, nullptr);

    // 5) LN2 -> z split
    ln_kernel<<<M_, 256>>>(y, ln2_g, ln2_b, zh, zl);

    // 6) FFN up + ReLU -> h split (bf16); ALSO normalizes attn rows (hidden under MMA)
    mm_hmma<EPI_BIAS_RELU, 1><<<dim3(DFF_ / 128, M_ / 128), 256, mm_smem>>>(
        zh, zl, w1h, w1l, nullptr, hh, hl, w1_b, nullptr, M_, DFF_, D_, attn_out, rsum);

    // 7) FFN down + bias + residual -> final y
    mm_hmma<EPI_BIAS_RES, 0><<<dim3(D_ / 128, M_ / 128), 256, mm_smem>>>(
        hh, hl, w2h, w2l, y_out, nullptr, nullptr, w2_b, y, M_, D_, DFF_, nullptr, nullptr);
}

// round 6
// speedup vs baseline: 3.0950x; 1.0443x over previous
#include <cuda_runtime.h>
#include <cuda_bf16.h>
#include <stdint.h>
#include <math.h>

#define B_   4
#define L_   2048
#define D_   1024
#define H_   16
#define DK_  64
#define DFF_ 4096
#define M_   (B_*L_)    // 8192 rows
#define BH_  (B_*H_)    // 64
#define QKVN (3*D_)     // 3072
#define QT_  128        // q rows per attention CTA

// ---------------- scratch (static device globals; no allocation) ----------------
__device__ __nv_bfloat16 g_xh[M_*D_],  g_xl[M_*D_];    // LN1 out split
__device__ __nv_bfloat16 g_zh[M_*D_],  g_zl[M_*D_];    // LN2 out split
__device__ __nv_bfloat16 g_oh[M_*D_],  g_ol[M_*D_];    // attn O split
__device__ __nv_bfloat16 g_hh[M_*DFF_],g_hl[M_*DFF_];  // FFN hidden split
__device__ __nv_bfloat16 g_qkvh[3*(size_t)M_*D_], g_qkvl[3*(size_t)M_*D_]; // packed [3][b,h,l,dk]
__device__ float g_y[M_*D_];
__device__ float g_rowsum[BH_*L_];
// weight splits (qkv combined rows 0..1023=Q, 1024..2047=K, 2048..3071=V)
__device__ __nv_bfloat16 g_wqkvh[QKVN*D_], g_wqkvl[QKVN*D_];
__device__ __nv_bfloat16 g_fch[D_*H_*DK_], g_fcl[D_*H_*DK_];
__device__ __nv_bfloat16 g_w1h[DFF_*D_],   g_w1l[DFF_*D_];
__device__ __nv_bfloat16 g_w2h[D_*DFF_],   g_w2l[D_*DFF_];

// ---------------- small PTX helpers ----------------
static __device__ __forceinline__ uint32_t s2u(const void* p) {
    uint32_t a;
    asm("{ .reg .u64 t; cvta.to.shared.u64 t, %1; cvt.u32.u64 %0, t; }" : "=r"(a) : "l"(p));
    return a;
}
static __device__ __forceinline__ void cp16(uint32_t dst, const void* src) {
    asm volatile("cp.async.cg.shared.global [%0], [%1], 16;" :: "r"(dst), "l"(src) : "memory");
}
static __device__ __forceinline__ void cp_commit() { asm volatile("cp.async.commit_group;" ::: "memory"); }
static __device__ __forceinline__ void cp_wait1()  { asm volatile("cp.async.wait_group 1;" ::: "memory"); }
static __device__ __forceinline__ void cp_wait0()  { asm volatile("cp.async.wait_group 0;" ::: "memory"); }

static __device__ __forceinline__ void ldsm_x4(uint32_t* r, uint32_t addr) {
    asm volatile("ldmatrix.sync.aligned.m8n8.x4.shared.b16 {%0,%1,%2,%3}, [%4];"
                 : "=r"(r[0]), "=r"(r[1]), "=r"(r[2]), "=r"(r[3]) : "r"(addr));
}
static __device__ __forceinline__ void ldsm_x4t(uint32_t* r, uint32_t addr) {
    asm volatile("ldmatrix.sync.aligned.m8n8.x4.trans.shared.b16 {%0,%1,%2,%3}, [%4];"
                 : "=r"(r[0]), "=r"(r[1]), "=r"(r[2]), "=r"(r[3]) : "r"(addr));
}
static __device__ __forceinline__ void mma16816(float* d, const uint32_t* a, const uint32_t* b) {
    asm volatile("mma.sync.aligned.m16n8k16.row.col.f32.bf16.bf16.f32 "
                 "{%0,%1,%2,%3}, {%4,%5,%6,%7}, {%8,%9}, {%0,%1,%2,%3};"
                 : "+f"(d[0]), "+f"(d[1]), "+f"(d[2]), "+f"(d[3])
                 : "r"(a[0]), "r"(a[1]), "r"(a[2]), "r"(a[3]), "r"(b[0]), "r"(b[1]));
}

static __device__ __forceinline__ uint32_t pack_hi(float a, float b, float* la, float* lb) {
    __nv_bfloat16 h0 = __float2bfloat16(a), h1 = __float2bfloat16(b);
    *la = a - __bfloat162float(h0);
    *lb = b - __bfloat162float(h1);
    __nv_bfloat162 hp = __halves2bfloat162(h0, h1);
    return *(uint32_t*)&hp;
}
static __device__ __forceinline__ uint32_t pack_lo(float a, float b) {
    __nv_bfloat162 lp = __floats2bfloat162_rn(a, b);
    return *(uint32_t*)&lp;
}

// split floats -> hi/lo bf16 stores
static __device__ __forceinline__ void split_store4(__nv_bfloat16* __restrict__ Hp,
                                                    __nv_bfloat16* __restrict__ Lp,
                                                    size_t idx, float4 v) {
    __nv_bfloat16 h0 = __float2bfloat16(v.x), h1 = __float2bfloat16(v.y);
    __nv_bfloat16 h2 = __float2bfloat16(v.z), h3 = __float2bfloat16(v.w);
    float l0 = v.x - __bfloat162float(h0), l1 = v.y - __bfloat162float(h1);
    float l2 = v.z - __bfloat162float(h2), l3 = v.w - __bfloat162float(h3);
    __nv_bfloat162 hp0 = __halves2bfloat162(h0, h1), hp1 = __halves2bfloat162(h2, h3);
    __nv_bfloat162 lp0 = __floats2bfloat162_rn(l0, l1), lp1 = __floats2bfloat162_rn(l2, l3);
    uint2 hu = make_uint2(*(uint32_t*)&hp0, *(uint32_t*)&hp1);
    uint2 lu = make_uint2(*(uint32_t*)&lp0, *(uint32_t*)&lp1);
    *(uint2*)(Hp + idx) = hu;
    *(uint2*)(Lp + idx) = lu;
}
static __device__ __forceinline__ void split_store2(__nv_bfloat16* __restrict__ Hp,
                                                    __nv_bfloat16* __restrict__ Lp,
                                                    size_t idx, float a, float b) {
    __nv_bfloat16 h0 = __float2bfloat16(a), h1 = __float2bfloat16(b);
    float l0 = a - __bfloat162float(h0), l1 = b - __bfloat162float(h1);
    __nv_bfloat162 hp = __halves2bfloat162(h0, h1);
    __nv_bfloat162 lp = __floats2bfloat162_rn(l0, l1);
    *(uint32_t*)(Hp + idx) = *(uint32_t*)&hp;
    *(uint32_t*)(Lp + idx) = *(uint32_t*)&lp;
}

// ---------------- weight split: fp32 -> bf16 hi/lo ----------------
__global__ __launch_bounds__(256) void split_kernel(const float* __restrict__ in,
                                                    __nv_bfloat16* __restrict__ Hp,
                                                    __nv_bfloat16* __restrict__ Lp,
                                                    int n4) {
    int i = blockIdx.x * 256 + threadIdx.x;
    if (i < n4) {
        float4 v = ((const float4*)in)[i];
        split_store4(Hp, Lp, (size_t)i * 4, v);
    }
}

// ---------------- LayerNorm -> bf16 hi/lo ----------------
__global__ __launch_bounds__(256) void ln_kernel(const float* __restrict__ in,
                                                 const float* __restrict__ g,
                                                 const float* __restrict__ b,
                                                 __nv_bfloat16* __restrict__ outH,
                                                 __nv_bfloat16* __restrict__ outL) {
    int row = blockIdx.x;
    const float4* inr = (const float4*)(in + (size_t)row * D_);
    float4 v = inr[threadIdx.x];
    float s  = v.x + v.y + v.z + v.w;
    float ss = v.x*v.x + v.y*v.y + v.z*v.z + v.w*v.w;
    #pragma unroll
    for (int o = 16; o > 0; o >>= 1) {
        s  += __shfl_xor_sync(0xffffffffu, s,  o);
        ss += __shfl_xor_sync(0xffffffffu, ss, o);
    }
    __shared__ float red[16];
    __shared__ float mv[2];
    int w = threadIdx.x >> 5, ln = threadIdx.x & 31;
    if (ln == 0) { red[w] = s; red[w + 8] = ss; }
    __syncthreads();
    if (threadIdx.x == 0) {
        float a = 0.f, q = 0.f;
        #pragma unroll
        for (int i = 0; i < 8; i++) { a += red[i]; q += red[i + 8]; }
        float mu = a * (1.0f / D_);
        mv[0] = mu;
        mv[1] = rsqrtf(q * (1.0f / D_) - mu * mu + 1e-6f);
    }
    __syncthreads();
    float mu = mv[0], rs = mv[1];
    float4 gg = ((const float4*)g)[threadIdx.x];
    float4 bb = ((const float4*)b)[threadIdx.x];
    float4 o4;
    o4.x = (v.x - mu) * rs * gg.x + bb.x;
    o4.y = (v.y - mu) * rs * gg.y + bb.y;
    o4.z = (v.z - mu) * rs * gg.z + bb.z;
    o4.w = (v.w - mu) * rs * gg.w + bb.w;
    split_store4(outH, outL, (size_t)row * D_ + threadIdx.x * 4, o4);
}

// ---------------- HMMA bf16x3 NT GEMM: CTA 128x256, warp tile 64x64 ----------------
enum { EPI_QKV = 0, EPI_RES = 1, EPI_BIAS_RELU = 2, EPI_BIAS_RES = 3 };

#define GS_AH 0u
#define GS_AL 16384u
#define GS_BH 32768u
#define GS_BL 65536u
#define GSTG  98304u   // stage stride (96 KB)

static __device__ __forceinline__ void load_chunk256(uint32_t stage,
    const __nv_bfloat16* __restrict__ Ah, const __nv_bfloat16* __restrict__ Al,
    const __nv_bfloat16* __restrict__ Bh, const __nv_bfloat16* __restrict__ Bl,
    int bm, int bn, int kc, int K, int tid)
{
    #pragma unroll
    for (int it = 0; it < 4; it++) {     // A: 128 rows x 64 k
        int e = tid + it * 256;
        int row = e >> 3, seg = e & 7;
        uint32_t off = (uint32_t)(row * 128 + seg * 16);
        uint32_t sw  = off ^ ((off >> 3) & 0x70u);
        size_t ga = (size_t)(bm + row) * K + (size_t)kc * 64 + seg * 8;
        cp16(stage + GS_AH + sw, Ah + ga);
        cp16(stage + GS_AL + sw, Al + ga);
    }
    #pragma unroll
    for (int it = 0; it < 8; it++) {     // B: 256 rows x 64 k
        int e = tid + it * 256;
        int row = e >> 3, seg = e & 7;
        uint32_t off = (uint32_t)(row * 128 + seg * 16);
        uint32_t sw  = off ^ ((off >> 3) & 0x70u);
        size_t gb = (size_t)(bn + row) * K + (size_t)kc * 64 + seg * 8;
        cp16(stage + GS_BH + sw, Bh + gb);
        cp16(stage + GS_BL + sw, Bl + gb);
    }
}

// DO_NORM: per chunk, normalize a slice of attn (grid must be 1024 CTAs, nc=16).
template <int EPI, int DO_NORM>
__global__ __launch_bounds__(256, 1)
void mm_hmma(const __nv_bfloat16* __restrict__ Ah, const __nv_bfloat16* __restrict__ Al,
             const __nv_bfloat16* __restrict__ Bh, const __nv_bfloat16* __restrict__ Bl,
             float* __restrict__ outF,
             __nv_bfloat16* __restrict__ outH, __nv_bfloat16* __restrict__ outL,
             const float* __restrict__ bias, const float* __restrict__ res,
             int M, int N, int K,
             float* __restrict__ normA, const float* __restrict__ normR)
{
    extern __shared__ char smem[];
    uint32_t tiles = s2u(smem);
    int tid = threadIdx.x, wid = tid >> 5, lane = tid & 31;
    int bm = blockIdx.y * 128, bn = blockIdx.x * 256;
    int wm = wid & 1, wn = wid >> 1;       // warp 64m x 64n tile
    int g = lane >> 3, lr = lane & 7;

    float acc[4][8][4];
    #pragma unroll
    for (int mt = 0; mt < 4; mt++)
        #pragma unroll
        for (int nt = 0; nt < 8; nt++)
            #pragma unroll
            for (int j = 0; j < 4; j++) acc[mt][nt][j] = 0.f;

    const int nc = K >> 6;
    load_chunk256(tiles, Ah, Al, Bh, Bl, bm, bn, 0, K, tid);
    cp_commit();

    size_t ctaLin = (size_t)blockIdx.y * gridDim.x + blockIdx.x;

    for (int i = 0; i < nc; i++) {
        if (i > 0) __syncthreads();   // all warps done reading the stage about to be overwritten
        if (i + 1 < nc) {
            load_chunk256(tiles + (uint32_t)((i + 1) & 1) * GSTG, Ah, Al, Bh, Bl, bm, bn, i + 1, K, tid);
            cp_commit();
            cp_wait1();
        } else {
            cp_wait0();
        }
        __syncthreads();

        uint32_t st = tiles + (uint32_t)(i & 1) * GSTG;
        uint32_t stAh = st + GS_AH, stAl = st + GS_AL, stBh = st + GS_BH, stBl = st + GS_BL;

        #pragma unroll
        for (int half = 0; half < 2; half++) {
            float4 nv[8]; float ni[8];
            if (DO_NORM) {
                size_t f4b = ctaLin * 65536u + (size_t)i * 4096u + (size_t)half * 2048u + (size_t)tid;
                #pragma unroll
                for (int j = 0; j < 8; j++) {
                    size_t f = f4b + (size_t)(j * 256);
                    nv[j] = __ldcs((const float4*)normA + f);
                    ni[j] = normR[f >> 9];
                }
            }
            #pragma unroll
            for (int kss = 0; kss < 2; kss++) {
                int ks = half * 2 + kss;
                uint32_t ah[4][4], al[4][4];
                int ka = ks * 32 + (g >> 1) * 16;
                #pragma unroll
                for (int mt = 0; mt < 4; mt++) {
                    int arow = wm * 64 + mt * 16 + (g & 1) * 8 + lr;
                    uint32_t ao = (uint32_t)(arow * 128) + ((uint32_t)ka ^ (uint32_t)((arow & 7) << 4));
                    ldsm_x4(ah[mt], stAh + ao);
                    ldsm_x4(al[mt], stAl + ao);
                }
                #pragma unroll
                for (int ntp = 0; ntp < 4; ntp++) {
                    // x4 B: m0=(n-lo,k-lo) m1=(n-lo,k-hi) m2=(n-hi,k-lo) m3=(n-hi,k-hi)
                    int brow = wn * 64 + ntp * 16 + ((g >> 1) << 3) + lr;
                    uint32_t kb = (uint32_t)(ks * 32 + ((g & 1) << 4));
                    uint32_t bo = (uint32_t)(brow * 128) + (kb ^ (uint32_t)((brow & 7) << 4));
                    uint32_t b4h[4], b4l[4];
                    ldsm_x4(b4h, stBh + bo);
                    ldsm_x4(b4l, stBl + bo);
                    #pragma unroll
                    for (int mt = 0; mt < 4; mt++) {
                        mma16816(acc[mt][2*ntp],   ah[mt], b4h);
                        mma16816(acc[mt][2*ntp],   ah[mt], b4l);
                        mma16816(acc[mt][2*ntp],   al[mt], b4h);
                        mma16816(acc[mt][2*ntp+1], ah[mt], b4h + 2);
                        mma16816(acc[mt][2*ntp+1], ah[mt], b4l + 2);
                        mma16816(acc[mt][2*ntp+1], al[mt], b4h + 2);
                    }
                }
            }
            if (DO_NORM) {
                size_t f4b = ctaLin * 65536u + (size_t)i * 4096u + (size_t)half * 2048u + (size_t)tid;
                #pragma unroll
                for (int j = 0; j < 8; j++) {
                    size_t f = f4b + (size_t)(j * 256);
                    float inv = 1.0f / ni[j];
                    float4 v = nv[j];
                    v.x *= inv; v.y *= inv; v.z *= inv; v.w *= inv;
                    __stcs((float4*)normA + f, v);
                }
            }
        }
    }

    int r = lane >> 2, c = lane & 3;
    #pragma unroll
    for (int mt = 0; mt < 4; mt++) {
        int m0 = bm + wm * 64 + mt * 16 + r;
        #pragma unroll
        for (int nt = 0; nt < 8; nt++) {
            int n = bn + wn * 64 + nt * 8 + c * 2;
            float d0 = acc[mt][nt][0], d1 = acc[mt][nt][1];
            float d2 = acc[mt][nt][2], d3 = acc[mt][nt][3];
            if (EPI == EPI_QKV) {
                int mat = n >> 10, nn = n & 1023;
                int bb = m0 >> 11, l = m0 & 2047, hh = nn >> 6, dd = nn & 63;
                size_t base = (size_t)mat * ((size_t)BH_ * L_ * DK_)
                            + (((size_t)(bb * H_ + hh) * L_ + l) * DK_ + dd);
                split_store2(outH, outL, base, d0, d1);
                split_store2(outH, outL, base + 8 * DK_, d2, d3);
            } else if (EPI == EPI_RES) {
                size_t off = (size_t)m0 * N + n;
                float2 r0 = *(const float2*)(res + off);
                float2 r1 = *(const float2*)(res + off + 8*(size_t)N);
                *(float2*)(outF + off)              = make_float2(d0 + r0.x, d1 + r0.y);
                *(float2*)(outF + off + 8*(size_t)N)= make_float2(d2 + r1.x, d3 + r1.y);
            } else if (EPI == EPI_BIAS_RELU) {
                size_t off = (size_t)m0 * N + n;
                float2 bv = *(const float2*)(bias + n);
                split_store2(outH, outL, off,
                             fmaxf(d0 + bv.x, 0.f), fmaxf(d1 + bv.y, 0.f));
                split_store2(outH, outL, off + 8*(size_t)N,
                             fmaxf(d2 + bv.x, 0.f), fmaxf(d3 + bv.y, 0.f));
            } else { // EPI_BIAS_RES
                size_t off = (size_t)m0 * N + n;
                float2 bv = *(const float2*)(bias + n);
                float2 r0 = *(const float2*)(res + off);
                float2 r1 = *(const float2*)(res + off + 8*(size_t)N);
                *(float2*)(outF + off)               = make_float2(d0 + bv.x + r0.x, d1 + bv.y + r0.y);
                *(float2*)(outF + off + 8*(size_t)N) = make_float2(d2 + bv.x + r1.x, d3 + bv.y + r1.y);
            }
        }
    }
}

// ---------------- HMMA fused attention (3-stage pipeline) ----------------
#define AS_QH   0u
#define AS_QL   16384u
#define AS_ST   32768u
#define AS_MSK  131072u
#define AS_RS   139264u
#define AS_TOT  (139264 + 512)

static __device__ __forceinline__ void attn_load_tile(uint32_t stn,
    const __nv_bfloat16* __restrict__ Kh, const __nv_bfloat16* __restrict__ Kl,
    const __nv_bfloat16* __restrict__ Vh, const __nv_bfloat16* __restrict__ Vl,
    size_t kbn, int tid)
{
    #pragma unroll
    for (int it = 0; it < 2; it++) {
        int e = tid + it * 256;
        int row = e >> 3, seg = e & 7;
        uint32_t off = (uint32_t)(row * 128 + seg * 16);
        uint32_t sw = off ^ ((off >> 3) & 0x70u);
        size_t gg = kbn + row * DK_ + seg * 8;
        cp16(stn +      0u + sw, Kh + gg);
        cp16(stn +  8192u + sw, Kl + gg);
        cp16(stn + 16384u + sw, Vh + gg);
        cp16(stn + 24576u + sw, Vl + gg);
    }
}

__global__ __launch_bounds__(256, 1)
void attn_mma(const __nv_bfloat16* __restrict__ Qh, const __nv_bfloat16* __restrict__ Ql,
              const __nv_bfloat16* __restrict__ Kh, const __nv_bfloat16* __restrict__ Kl,
              const __nv_bfloat16* __restrict__ Vh, const __nv_bfloat16* __restrict__ Vl,
              const float* __restrict__ prior, const int* __restrict__ mask,
              float* __restrict__ attn,
              __nv_bfloat16* __restrict__ Oh, __nv_bfloat16* __restrict__ Ol,
              float* __restrict__ rowsum)
{
    extern __shared__ char smc[];
    uint32_t sb = s2u(smc);
    float* msk = (float*)(smc + AS_MSK);
    float* rs  = (float*)(smc + AS_RS);

    int tid = threadIdx.x, warp = tid >> 5, lane = tid & 31;
    int qt = blockIdx.x, h = blockIdx.y, b = blockIdx.z;
    int bh = b * H_ + h;
    size_t qbase = ((size_t)bh * L_ + (size_t)qt * QT_) * DK_;
    size_t kvbase = (size_t)bh * L_ * DK_;

    for (int i = tid; i < L_; i += 256) msk[i] = mask[b * L_ + i] ? 1.0f : 0.0f;
    if (tid < QT_) rs[tid] = 0.f;

    #pragma unroll
    for (int it = 0; it < 4; it++) {
        int e = tid + it * 256;
        int row = e >> 3, seg = e & 7;
        uint32_t off = (uint32_t)(row * 128 + seg * 16);
        uint32_t sw = off ^ ((off >> 3) & 0x70u);
        cp16(sb + AS_QH + sw, Qh + qbase + row * DK_ + seg * 8);
        cp16(sb + AS_QL + sw, Ql + qbase + row * DK_ + seg * 8);
    }
    attn_load_tile(sb + AS_ST, Kh, Kl, Vh, Vl, kvbase, tid);
    cp_commit();
    attn_load_tile(sb + AS_ST + 32768u, Kh, Kl, Vh, Vl, kvbase + 64 * DK_, tid);
    cp_commit();

    float accO[8][4];
    #pragma unroll
    for (int nt = 0; nt < 8; nt++)
        #pragma unroll
        for (int j = 0; j < 4; j++) accO[nt][j] = 0.f;

    uint32_t qfh[4][4], qfl[4][4];

    int g = lane >> 3, lr = lane & 7;
    int r = lane >> 2, ci = lane & 3;
    int q0 = qt * QT_ + warp * 16 + r;
    const float* prow0 = prior + ((size_t)b * L_ + q0) * L_;
    const float* prow1 = prow0 + 8 * (size_t)L_;
    float* arow0 = attn + ((size_t)bh * L_ + q0) * L_;
    float* arow1 = arow0 + 8 * (size_t)L_;

    const int NKT = L_ / 64;  // 32
    for (int kt = 0; kt < NKT; kt++) {
        if (kt == NKT - 1) cp_wait0(); else cp_wait1();
        __syncthreads();
        if (kt + 2 < NKT) {
            attn_load_tile(sb + AS_ST + (uint32_t)((kt + 2) % 3) * 32768u,
                           Kh, Kl, Vh, Vl, kvbase + (size_t)(kt + 2) * 64 * DK_, tid);
            cp_commit();
        }

        if (kt == 0) {
            #pragma unroll
            for (int ks = 0; ks < 4; ks++) {
                int arow = warp * 16 + (g & 1) * 8 + lr;
                uint32_t ka = (uint32_t)(ks * 32 + (g >> 1) * 16);
                uint32_t ao = (uint32_t)(arow * 128) + (ka ^ (uint32_t)((arow & 7) << 4));
                ldsm_x4(qfh[ks], sb + AS_QH + ao);
                ldsm_x4(qfl[ks], sb + AS_QL + ao);
            }
        }

        uint32_t st = sb + AS_ST + (uint32_t)(kt % 3) * 32768u;

        // prefetch prior for this ktile into registers (hidden under QK MMAs)
        int k0 = kt * 64;
        float2 pA[8], pB[8];
        #pragma unroll
        for (int nt = 0; nt < 8; nt++) {
            int kk = k0 + nt * 8 + ci * 2;
            pA[nt] = __ldcs((const float2*)(prow0 + kk));
            pB[nt] = __ldcs((const float2*)(prow1 + kk));
        }

        // --- QK^T ---
        float accS[8][4];
        #pragma unroll
        for (int nt = 0; nt < 8; nt++)
            #pragma unroll
            for (int j = 0; j < 4; j++) accS[nt][j] = 0.f;

        #pragma unroll
        for (int ks = 0; ks < 4; ks++) {
            #pragma unroll
            for (int ntp = 0; ntp < 4; ntp++) {
                int brow = ntp * 16 + ((g >> 1) << 3) + lr;
                uint32_t kb = (uint32_t)(ks * 32 + ((g & 1) << 4));
                uint32_t bo = (uint32_t)(brow * 128) + (kb ^ (uint32_t)((brow & 7) << 4));
                uint32_t k4h[4], k4l[4];
                ldsm_x4(k4h, st + bo);
                ldsm_x4(k4l, st + 8192u + bo);
                mma16816(accS[2*ntp],   qfh[ks], k4h);
                mma16816(accS[2*ntp],   qfh[ks], k4l);
                mma16816(accS[2*ntp],   qfl[ks], k4h);
                mma16816(accS[2*ntp+1], qfh[ks], k4h + 2);
                mma16816(accS[2*ntp+1], qfh[ks], k4l + 2);
                mma16816(accS[2*ntp+1], qfl[ks], k4h + 2);
            }
        }

        // --- prior * mask * exp, attn store (.cs), rowsum, pack P frags ---
        float sum0 = 0.f, sum1 = 0.f;
        uint32_t ph[4][4], pl[4][4];
        #pragma unroll
        for (int nt = 0; nt < 8; nt++) {
            int kk = k0 + nt * 8 + ci * 2;
            float mk0 = msk[kk], mk1 = msk[kk + 1];
            float e0 = mk0 * __expf(accS[nt][0] * 0.125f * pA[nt].x);
            float e1 = mk1 * __expf(accS[nt][1] * 0.125f * pA[nt].y);
            float e2 = mk0 * __expf(accS[nt][2] * 0.125f * pB[nt].x);
            float e3 = mk1 * __expf(accS[nt][3] * 0.125f * pB[nt].y);
            __stcs((float2*)(arow0 + kk), make_float2(e0, e1));
            __stcs((float2*)(arow1 + kk), make_float2(e2, e3));
            sum0 += e0 + e1;
            sum1 += e2 + e3;
            int t = nt >> 1, o = (nt & 1) * 2;
            float l0, l1, l2, l3;
            ph[t][o]     = pack_hi(e0, e1, &l0, &l1);
            ph[t][o + 1] = pack_hi(e2, e3, &l2, &l3);
            pl[t][o]     = pack_lo(l0, l1);
            pl[t][o + 1] = pack_lo(l2, l3);
        }
        sum0 += __shfl_xor_sync(0xffffffffu, sum0, 1);
        sum0 += __shfl_xor_sync(0xffffffffu, sum0, 2);
        sum1 += __shfl_xor_sync(0xffffffffu, sum1, 1);
        sum1 += __shfl_xor_sync(0xffffffffu, sum1, 2);
        if (ci == 0) {
            rs[warp * 16 + r]     += sum0;
            rs[warp * 16 + r + 8] += sum1;
        }

        // --- P @ V (x4 trans V loads) ---
        #pragma unroll
        for (int t2 = 0; t2 < 2; t2++) {
            #pragma unroll
            for (int nt = 0; nt < 8; nt++) {
                int vrow = t2 * 32 + lane;
                uint32_t vo = (uint32_t)(vrow * 128) + ((uint32_t)(nt * 16) ^ (uint32_t)((vrow & 7) << 4));
                uint32_t v4h[4], v4l[4];
                ldsm_x4t(v4h, st + 16384u + vo);
                ldsm_x4t(v4l, st + 24576u + vo);
                mma16816(accO[nt], ph[2*t2],   v4h);
                mma16816(accO[nt], pl[2*t2],   v4h);
                mma16816(accO[nt], ph[2*t2],   v4l);
                mma16816(accO[nt], ph[2*t2+1], v4h + 2);
                mma16816(accO[nt], pl[2*t2+1], v4h + 2);
                mma16816(accO[nt], ph[2*t2+1], v4l + 2);
            }
        }
    }
    __syncthreads();

    int row0 = warp * 16 + r;
    float inv0 = 1.0f / rs[row0], inv1 = 1.0f / rs[row0 + 8];
    int l0 = qt * QT_ + row0;
    if (ci == 0) {
        rowsum[(size_t)bh * L_ + l0]     = rs[row0];
        rowsum[(size_t)bh * L_ + l0 + 8] = rs[row0 + 8];
    }
    #pragma unroll
    for (int nt = 0; nt < 8; nt++) {
        int dv = nt * 8 + ci * 2;
        size_t o0 = ((size_t)b * L_ + l0) * D_ + h * 64 + dv;
        size_t o1 = o0 + 8 * (size_t)D_;
        split_store2(Oh, Ol, o0, accO[nt][0] * inv0, accO[nt][1] * inv0);
        split_store2(Oh, Ol, o1, accO[nt][2] * inv1, accO[nt][3] * inv1);
    }
}

// ---------------- host launcher ----------------
extern "C" void kernel_launch(void* const* d_in, const int* in_sizes, int n_in,
                              void* d_out, int out_size) {
    const float* src   = (const float*)d_in[0];
    const int*   mask  = (const int*)d_in[1];
    const float* prior = (const float*)d_in[2];
    const float* ln1_g = (const float*)d_in[3];
    const float* ln1_b = (const float*)d_in[4];
    const float* wq    = (const float*)d_in[5];
    const float* wk    = (const float*)d_in[6];
    const float* wv    = (const float*)d_in[7];
    const float* fc_w  = (const float*)d_in[8];
    const float* ln2_g = (const float*)d_in[9];
    const float* ln2_b = (const float*)d_in[10];
    const float* w1_w  = (const float*)d_in[11];
    const float* w1_b  = (const float*)d_in[12];
    const float* w2_w  = (const float*)d_in[13];
    const float* w2_b  = (const float*)d_in[14];

    float* out      = (float*)d_out;
    float* y_out    = out;                       // [B,L,D]
    float* attn_out = out + (size_t)M_ * D_;     // [B,H,L,L]

    __nv_bfloat16 *xh, *xl, *zh, *zl, *oh, *ol, *hh, *hl, *qkvh, *qkvl;
    __nv_bfloat16 *wqkvh, *wqkvl, *fch, *fcl, *w1h, *w1l, *w2h, *w2l;
    float *y, *rsum;
    cudaGetSymbolAddress((void**)&xh, g_xh);  cudaGetSymbolAddress((void**)&xl, g_xl);
    cudaGetSymbolAddress((void**)&zh, g_zh);  cudaGetSymbolAddress((void**)&zl, g_zl);
    cudaGetSymbolAddress((void**)&oh, g_oh);  cudaGetSymbolAddress((void**)&ol, g_ol);
    cudaGetSymbolAddress((void**)&hh, g_hh);  cudaGetSymbolAddress((void**)&hl, g_hl);
    cudaGetSymbolAddress((void**)&qkvh, g_qkvh); cudaGetSymbolAddress((void**)&qkvl, g_qkvl);
    cudaGetSymbolAddress((void**)&wqkvh, g_wqkvh); cudaGetSymbolAddress((void**)&wqkvl, g_wqkvl);
    cudaGetSymbolAddress((void**)&fch, g_fch); cudaGetSymbolAddress((void**)&fcl, g_fcl);
    cudaGetSymbolAddress((void**)&w1h, g_w1h); cudaGetSymbolAddress((void**)&w1l, g_w1l);
    cudaGetSymbolAddress((void**)&w2h, g_w2h); cudaGetSymbolAddress((void**)&w2l, g_w2l);
    cudaGetSymbolAddress((void**)&y, g_y);
    cudaGetSymbolAddress((void**)&rsum, g_rowsum);

    const int mm_smem = 2 * GSTG;   // 192 KB
    cudaFuncSetAttribute(mm_hmma<EPI_QKV, 0>,       cudaFuncAttributeMaxDynamicSharedMemorySize, mm_smem);
    cudaFuncSetAttribute(mm_hmma<EPI_RES, 0>,       cudaFuncAttributeMaxDynamicSharedMemorySize, mm_smem);
    cudaFuncSetAttribute(mm_hmma<EPI_BIAS_RELU, 1>, cudaFuncAttributeMaxDynamicSharedMemorySize, mm_smem);
    cudaFuncSetAttribute(mm_hmma<EPI_BIAS_RES, 0>,  cudaFuncAttributeMaxDynamicSharedMemorySize, mm_smem);
    cudaFuncSetAttribute(attn_mma,                  cudaFuncAttributeMaxDynamicSharedMemorySize, AS_TOT);

    // 0) split weights to bf16 hi/lo (QKV concatenated)
    split_kernel<<<1024, 256>>>(wq,   wqkvh,                   wqkvl,                   (D_*D_) / 4);
    split_kernel<<<1024, 256>>>(wk,   wqkvh + (size_t)D_*D_,   wqkvl + (size_t)D_*D_,   (D_*D_) / 4);
    split_kernel<<<1024, 256>>>(wv,   wqkvh + 2*(size_t)D_*D_, wqkvl + 2*(size_t)D_*D_, (D_*D_) / 4);
    split_kernel<<<1024, 256>>>(fc_w, fch, fcl, (D_*H_*DK_) / 4);
    split_kernel<<<4096, 256>>>(w1_w, w1h, w1l, (DFF_*D_) / 4);
    split_kernel<<<4096, 256>>>(w2_w, w2h, w2l, (D_*DFF_) / 4);

    // 1) LN1 -> x split
    ln_kernel<<<M_, 256>>>(src, ln1_g, ln1_b, xh, xl);

    // 2) fused QKV projection (N=3072) -> bf16 hi/lo packed [3][b,h,l,dk]
    mm_hmma<EPI_QKV, 0><<<dim3(QKVN / 256, M_ / 128), 256, mm_smem>>>(
        xh, xl, wqkvh, wqkvl, nullptr, qkvh, qkvl, nullptr, nullptr, M_, QKVN, D_, nullptr, nullptr);

    const size_t QS = (size_t)BH_ * L_ * DK_;
    // 3) HMMA fused attention (unnormalized attn + rowsum + normalized O)
    dim3 gattn(L_ / QT_, H_, B_);
    attn_mma<<<gattn, 256, AS_TOT>>>(qkvh, qkvl, qkvh + QS, qkvl + QS, qkvh + 2*QS, qkvl + 2*QS,
                                     prior, mask, attn_out, oh, ol, rsum);

    // 4) fc + residual -> y (fp32)
    mm_hmma<EPI_RES, 0><<<dim3(D_ / 256, M_ / 128), 256, mm_smem>>>(
        oh, ol, fch, fcl, y, nullptr, nullptr, nullptr, src, M_, D_, D_, nullptr, nullptr);

    // 5) LN2 -> z split
    ln_kernel<<<M_, 256>>>(y, ln2_g, ln2_b, zh, zl);

    // 6) FFN up + ReLU -> h split; ALSO normalizes attn rows (hidden under MMA)
    mm_hmma<EPI_BIAS_RELU, 1><<<dim3(DFF_ / 256, M_ / 128), 256, mm_smem>>>(
        zh, zl, w1h, w1l, nullptr, hh, hl, w1_b, nullptr, M_, DFF_, D_, attn_out, rsum);

    // 7) FFN down + bias + residual -> final y
    mm_hmma<EPI_BIAS_RES, 0><<<dim3(D_ / 256, M_ / 128), 256, mm_smem>>>(
        hh, hl, w2h, w2l, y_out, nullptr, nullptr, w2_b, y, M_, D_, DFF_, nullptr, nullptr);
}